// round 7
// baseline (speedup 1.0000x reference)
#include <cuda_runtime.h>
#include <math.h>

#define BATCH 4
#define NPTS  4096
#define M1    2048
#define M2    410
#define KNN   64
#define R1 (BATCH*M1*KNN)   /* 524288 */
#define R2 (BATCH*M2*KNN)   /* 104960 */
#define R3 (BATCH*M2)       /* 1640   */

// ---------------- static scratch (no allocations allowed) ----------------
__device__ float g_qpos1[BATCH*M1*3];
__device__ float g_qpos2[BATCH*M2*3];
__device__ int   g_nidx1[R1];
__device__ float g_nd2_1[R1];
__device__ int   g_nidx2[R2];
__device__ float g_nd2_2[R2];
__device__ float g_x1[BATCH*M1*128];
__device__ float g_x2[BATCH*M2*512];
__device__ float g_glob[BATCH*1024];
__device__ float g_bufX[13749760];   // max(R1*6, R2*131, R3*515)
__device__ float g_bufA[33554432];   // max(R1*64, R2*128, R3*1024)
__device__ float g_bufB[33554432];   // max(R1*64, R2*256)

// =====================================================================
// Farthest point sampling. One block per batch, 512 threads,
// register-resident positions + min-dists. Matches jnp semantics:
// dists init +inf, start idx 0, argmax with first-index tie-break.
// =====================================================================
__global__ void __launch_bounds__(512) fps_kernel(const float* __restrict__ pos,
                                                  int n, int m,
                                                  float* __restrict__ qpos)
{
    const int b = blockIdx.x;
    const float* P = pos + (size_t)b * n * 3;
    float* Q = qpos + (size_t)b * m * 3;
    const int tid = threadIdx.x;
    const float INF = __int_as_float(0x7f800000);

    float px[8], py[8], pz[8], md[8];
#pragma unroll
    for (int j = 0; j < 8; j++) {
        int i = tid + j * 512;
        if (i < n) { px[j] = P[i*3]; py[j] = P[i*3+1]; pz[j] = P[i*3+2]; }
        else       { px[j] = 0.f;   py[j] = 0.f;      pz[j] = 0.f; }
        md[j] = INF;
    }

    __shared__ float s_last[3];
    __shared__ float s_wv[16];
    __shared__ int   s_wi[16];
    if (tid == 0) {
        s_last[0] = P[0]; s_last[1] = P[1]; s_last[2] = P[2];
        Q[0] = P[0]; Q[1] = P[1]; Q[2] = P[2];
    }
    __syncthreads();

    for (int it = 1; it < m; it++) {
        float lx = s_last[0], ly = s_last[1], lz = s_last[2];
        float bv = -1.0f; int bi = 0x7fffffff;
#pragma unroll
        for (int j = 0; j < 8; j++) {
            int i = tid + j * 512;
            if (i < n) {
                float dx = __fadd_rn(px[j], -lx);
                float dy = __fadd_rn(py[j], -ly);
                float dz = __fadd_rn(pz[j], -lz);
                float d  = __fadd_rn(__fadd_rn(__fmul_rn(dx,dx), __fmul_rn(dy,dy)),
                                     __fmul_rn(dz,dz));
                float mm = fminf(md[j], d);
                md[j] = mm;
                if (mm > bv) { bv = mm; bi = i; } // j asc => i asc => first-max kept
            }
        }
#pragma unroll
        for (int off = 16; off > 0; off >>= 1) {
            float ov = __shfl_down_sync(0xffffffffu, bv, off);
            int   oi = __shfl_down_sync(0xffffffffu, bi, off);
            if (ov > bv || (ov == bv && oi < bi)) { bv = ov; bi = oi; }
        }
        if ((tid & 31) == 0) { s_wv[tid >> 5] = bv; s_wi[tid >> 5] = bi; }
        __syncthreads();
        if (tid < 32) {
            bv = (tid < 16) ? s_wv[tid] : -1.0f;
            bi = (tid < 16) ? s_wi[tid] : 0x7fffffff;
#pragma unroll
            for (int off = 8; off > 0; off >>= 1) {
                float ov = __shfl_down_sync(0xffffffffu, bv, off);
                int   oi = __shfl_down_sync(0xffffffffu, bi, off);
                if (ov > bv || (ov == bv && oi < bi)) { bv = ov; bi = oi; }
            }
            if (tid == 0) {
                float qx = P[bi*3], qy = P[bi*3+1], qz = P[bi*3+2];
                s_last[0] = qx; s_last[1] = qy; s_last[2] = qz;
                Q[(size_t)it*3]   = qx;
                Q[(size_t)it*3+1] = qy;
                Q[(size_t)it*3+2] = qz;
            }
        }
        __syncthreads();
    }
}

// =====================================================================
// Exact 64-NN per query. One block per query, 256 threads.
// d2 in smem; 64 iterative argmins; only the winner's owner rescans.
// Tie-break: lower index (matches lax.top_k stable ordering).
// =====================================================================
__global__ void __launch_bounds__(256) knn_kernel(const float* __restrict__ src,
                                                  const float* __restrict__ qpos,
                                                  int n, int m,
                                                  int* __restrict__ nidx,
                                                  float* __restrict__ nd2)
{
    extern __shared__ float sd[];   // n floats
    const int bq = blockIdx.x;      // b*m + q
    const int b  = bq / m;
    const float* S = src + (size_t)b * n * 3;
    const int tid = threadIdx.x;
    const float FMAX = 3.402823466e38f;

    float qx = qpos[(size_t)bq*3], qy = qpos[(size_t)bq*3+1], qz = qpos[(size_t)bq*3+2];
    for (int i = tid; i < n; i += 256) {
        float dx = __fadd_rn(S[i*3],   -qx);
        float dy = __fadd_rn(S[i*3+1], -qy);
        float dz = __fadd_rn(S[i*3+2], -qz);
        sd[i] = __fadd_rn(__fadd_rn(__fmul_rn(dx,dx), __fmul_rn(dy,dy)),
                          __fmul_rn(dz,dz));
    }
    __syncthreads();

    float lv = FMAX; int li = 0x7fffffff;
    for (int i = tid; i < n; i += 256) { float v = sd[i]; if (v < lv) { lv = v; li = i; } }

    __shared__ float swv[8];
    __shared__ int   swi[8];
    __shared__ int   s_sel;

    for (int k = 0; k < KNN; k++) {
        float bv = lv; int bi = li;
#pragma unroll
        for (int off = 16; off > 0; off >>= 1) {
            float ov = __shfl_down_sync(0xffffffffu, bv, off);
            int   oi = __shfl_down_sync(0xffffffffu, bi, off);
            if (ov < bv || (ov == bv && oi < bi)) { bv = ov; bi = oi; }
        }
        if ((tid & 31) == 0) { swv[tid >> 5] = bv; swi[tid >> 5] = bi; }
        __syncthreads();
        if (tid < 32) {
            bv = (tid < 8) ? swv[tid] : FMAX;
            bi = (tid < 8) ? swi[tid] : 0x7fffffff;
#pragma unroll
            for (int off = 4; off > 0; off >>= 1) {
                float ov = __shfl_down_sync(0xffffffffu, bv, off);
                int   oi = __shfl_down_sync(0xffffffffu, bi, off);
                if (ov < bv || (ov == bv && oi < bi)) { bv = ov; bi = oi; }
            }
            if (tid == 0) {
                s_sel = bi;
                nidx[(size_t)bq*KNN + k] = bi;
                nd2 [(size_t)bq*KNN + k] = bv;
            }
        }
        __syncthreads();
        int sel = s_sel;
        if ((sel & 255) == tid) {          // owner of that strided slot
            sd[sel] = FMAX;
            lv = FMAX; li = 0x7fffffff;
            for (int i = tid; i < n; i += 256) { float v = sd[i]; if (v < lv) { lv = v; li = i; } }
        }
    }
}

// =====================================================================
// Gather kernels: build MLP input rows
// =====================================================================
__global__ void gather1_kernel(const float* __restrict__ color,
                               const float* __restrict__ xyz)
{
    int r = blockIdx.x * 256 + threadIdx.x;
    if (r >= R1) return;
    int b = r >> 17;                 // M1*KNN = 131072
    int q = (r >> 6) & (M1 - 1);
    int n = g_nidx1[r];
    const float* cb = color + ((size_t)b*NPTS + n) * 3;
    const float* pb = xyz   + ((size_t)b*NPTS + n) * 3;
    const float* qp = g_qpos1 + ((size_t)(b*M1 + q)) * 3;
    float* o = g_bufX + (size_t)r * 6;
    o[0] = cb[0]; o[1] = cb[1]; o[2] = cb[2];
    o[3] = pb[0] - qp[0]; o[4] = pb[1] - qp[1]; o[5] = pb[2] - qp[2];
}

__global__ void gather2_kernel()
{
    int gt = blockIdx.x * 256 + threadIdx.x;
    int w = gt >> 5, lane = gt & 31;
    if (w >= R2) return;
    int b = w / (M2 * KNN);
    int q = (w / KNN) % M2;
    int n = g_nidx2[w];
    const float* xr = g_x1 + ((size_t)(b*M1 + n)) * 128;
    float* o = g_bufX + (size_t)w * 131;
#pragma unroll
    for (int i = 0; i < 4; i++) o[lane + 32*i] = xr[lane + 32*i];
    if (lane < 3)
        o[128 + lane] = g_qpos1[((size_t)(b*M1 + n))*3 + lane]
                      - g_qpos2[((size_t)(b*M2 + q))*3 + lane];
}

__global__ void gather3_kernel()
{
    int e = blockIdx.x * 256 + threadIdx.x;
    if (e >= R3 * 515) return;
    int row = e / 515, c = e % 515;
    g_bufX[e] = (c < 512) ? g_x2[(size_t)row*512 + c]
                          : g_qpos2[(size_t)row*3 + (c - 512)];
}

// =====================================================================
// Tiled SGEMM Y = bn(relu(X @ W + bias)) using packed fma.rn.f32x2.
// X [M,K] row-major, W [K,N] row-major, Y [M,N].
// BM=BN=64, BK=16, 128 threads, 8x4 microtile (rows packed in pairs).
// =====================================================================
#define BKK 16
__global__ void __launch_bounds__(128) gemm_bn(const float* __restrict__ X,
    const float* __restrict__ W, const float* __restrict__ bias,
    const float* __restrict__ gamma, const float* __restrict__ beta,
    float* __restrict__ Y, int M, int K, int N)
{
    __shared__ __align__(16) float As[BKK][64 + 4];
    __shared__ __align__(16) float Bs[BKK][64 + 4];
    const int tid = threadIdx.x;
    const int bm = blockIdx.y * 64, bn = blockIdx.x * 64;
    const int tn = (tid & 15) * 4;
    const int tm = (tid >> 4) * 8;

    unsigned long long acc[4][4];
#pragma unroll
    for (int i = 0; i < 4; i++)
#pragma unroll
        for (int j = 0; j < 4; j++) acc[i][j] = 0ull;

    for (int k0 = 0; k0 < K; k0 += BKK) {
#pragma unroll
        for (int i = 0; i < 8; i++) {
            int t = i*128 + tid;
            int m = t >> 4, k = t & 15;
            float v = 0.f;
            int gr = bm + m, gk = k0 + k;
            if (gr < M && gk < K) v = X[(size_t)gr*K + gk];
            As[k][m] = v;
        }
#pragma unroll
        for (int i = 0; i < 8; i++) {
            int t = i*128 + tid;
            int k = t >> 6, n = t & 63;
            float v = 0.f;
            int gk = k0 + k;
            if (gk < K) v = W[(size_t)gk*N + bn + n];
            Bs[k][n] = v;
        }
        __syncthreads();
#pragma unroll
        for (int kk = 0; kk < BKK; kk++) {
            unsigned long long a2[4], b2[4];
#pragma unroll
            for (int i = 0; i < 4; i++)
                a2[i] = *(const unsigned long long*)&As[kk][tm + 2*i];
#pragma unroll
            for (int j = 0; j < 4; j++) {
                float bv = Bs[kk][tn + j];
                asm("mov.b64 %0, {%1, %1};" : "=l"(b2[j]) : "f"(bv));
            }
#pragma unroll
            for (int i = 0; i < 4; i++)
#pragma unroll
                for (int j = 0; j < 4; j++)
                    asm("fma.rn.f32x2 %0, %1, %2, %0;"
                        : "+l"(acc[i][j]) : "l"(a2[i]), "l"(b2[j]));
        }
        __syncthreads();
    }

    const float bnf = 1.0f / sqrtf(1.0f + 1e-5f);
    float s[4], t[4], bi[4];
#pragma unroll
    for (int j = 0; j < 4; j++) {
        int c = bn + tn + j;
        s[j] = gamma[c] * bnf; t[j] = beta[c]; bi[j] = bias[c];
    }
#pragma unroll
    for (int i = 0; i < 4; i++) {
#pragma unroll
        for (int j = 0; j < 4; j++) {
            float lo, hi;
            asm("mov.b64 {%0, %1}, %2;" : "=f"(lo), "=f"(hi) : "l"(acc[i][j]));
            int r0 = bm + tm + 2*i;
            if (r0 < M) {
                float v = fmaxf(lo + bi[j], 0.f);
                Y[(size_t)r0*N + bn + tn + j] = v * s[j] + t[j];
            }
            if (r0 + 1 < M) {
                float v = fmaxf(hi + bi[j], 0.f);
                Y[(size_t)(r0+1)*N + bn + tn + j] = v * s[j] + t[j];
            }
        }
    }
}

// =====================================================================
// Masked max-aggregation over K neighbors, two radii per SA module.
// =====================================================================
__global__ void maxagg1_kernel()
{
    int bq = blockIdx.x, f = threadIdx.x;   // 64 threads
    const float rA = (float)(0.2*0.2), rB = (float)(0.1*0.1);
    float mA = -3.402823466e38f, mB = -3.402823466e38f;
    bool aA = false, aB = false;
    for (int k = 0; k < KNN; k++) {
        float d2 = g_nd2_1[(size_t)bq*KNN + k];
        float h  = g_bufB[((size_t)bq*KNN + k)*64 + f];
        if (d2 <= rA) { aA = true; mA = fmaxf(mA, h); }
        if (d2 <= rB) { aB = true; mB = fmaxf(mB, h); }
    }
    g_x1[(size_t)bq*128 + f]      = aA ? mA : 0.f;
    g_x1[(size_t)bq*128 + 64 + f] = aB ? mB : 0.f;
}

__global__ void maxagg2_kernel()
{
    int bq = blockIdx.x, f = threadIdx.x;   // 256 threads
    const float rA = (float)(0.35*0.35), rB = (float)(0.5*0.5);
    float mA = -3.402823466e38f, mB = -3.402823466e38f;
    bool aA = false, aB = false;
    for (int k = 0; k < KNN; k++) {
        float d2 = g_nd2_2[(size_t)bq*KNN + k];
        float h  = g_bufB[((size_t)bq*KNN + k)*256 + f];
        if (d2 <= rA) { aA = true; mA = fmaxf(mA, h); }
        if (d2 <= rB) { aB = true; mB = fmaxf(mB, h); }
    }
    g_x2[(size_t)bq*512 + f]       = aA ? mA : 0.f;
    g_x2[(size_t)bq*512 + 256 + f] = aB ? mB : 0.f;
}

__global__ void globalmax_kernel()
{
    int f = blockIdx.x * 256 + threadIdx.x;   // 1024 feats
    int b = blockIdx.y;
    float m = -3.402823466e38f;
    for (int q = 0; q < M2; q++)
        m = fmaxf(m, g_bufA[((size_t)(b*M2 + q))*1024 + f]);
    g_glob[(size_t)b*1024 + f] = m;
}

// =====================================================================
// Head: h1 = relu(g @ wl1 + bl1); out = h1 @ wl2 + bl2; L2-normalize.
// One block per batch, 512 threads.
// =====================================================================
__global__ void __launch_bounds__(512) head_kernel(
    const float* __restrict__ wl1, const float* __restrict__ bl1,
    const float* __restrict__ wl2, const float* __restrict__ bl2,
    float* __restrict__ out)
{
    __shared__ float sg[1024];
    __shared__ float sh[512];
    __shared__ float so[128];
    __shared__ float snorm;
    int b = blockIdx.x, tid = threadIdx.x;
    sg[tid]       = g_glob[(size_t)b*1024 + tid];
    sg[tid + 512] = g_glob[(size_t)b*1024 + 512 + tid];
    __syncthreads();

    float acc = bl1[tid];
    for (int k = 0; k < 1024; k++) acc = fmaf(sg[k], wl1[(size_t)k*512 + tid], acc);
    sh[tid] = fmaxf(acc, 0.f);
    __syncthreads();

    if (tid < 128) {
        float o = bl2[tid];
        for (int k = 0; k < 512; k++) o = fmaf(sh[k], wl2[(size_t)k*128 + tid], o);
        so[tid] = o;
    }
    __syncthreads();
    if (tid < 32) {
        float s = 0.f;
        for (int c = tid; c < 128; c += 32) s += so[c] * so[c];
#pragma unroll
        for (int off = 16; off > 0; off >>= 1) s += __shfl_down_sync(0xffffffffu, s, off);
        if (tid == 0) snorm = sqrtf(s);
    }
    __syncthreads();
    if (tid < 128) out[(size_t)b*128 + tid] = so[tid] / snorm;
}

// =====================================================================
extern "C" void kernel_launch(void* const* d_in, const int* in_sizes, int n_in,
                              void* d_out, int out_size)
{
    const float* xyz   = (const float*)d_in[0];
    const float* color = (const float*)d_in[1];
    const float* w1a = (const float*)d_in[2],  *b1a = (const float*)d_in[3];
    const float* g1a = (const float*)d_in[4],  *be1a = (const float*)d_in[5];
    const float* w1b = (const float*)d_in[6],  *b1b = (const float*)d_in[7];
    const float* g1b = (const float*)d_in[8],  *be1b = (const float*)d_in[9];
    const float* w2a = (const float*)d_in[10], *b2a = (const float*)d_in[11];
    const float* g2a = (const float*)d_in[12], *be2a = (const float*)d_in[13];
    const float* w2b = (const float*)d_in[14], *b2b = (const float*)d_in[15];
    const float* g2b = (const float*)d_in[16], *be2b = (const float*)d_in[17];
    const float* w3  = (const float*)d_in[18], *b3  = (const float*)d_in[19];
    const float* g3  = (const float*)d_in[20], *be3 = (const float*)d_in[21];
    const float* wl1 = (const float*)d_in[22], *bl1 = (const float*)d_in[23];
    const float* wl2 = (const float*)d_in[24], *bl2 = (const float*)d_in[25];
    float* out = (float*)d_out;

    void *vQ1, *vQ2, *vN1, *vD1, *vN2, *vD2, *vX, *vA, *vB;
    cudaGetSymbolAddress(&vQ1, g_qpos1);
    cudaGetSymbolAddress(&vQ2, g_qpos2);
    cudaGetSymbolAddress(&vN1, g_nidx1);
    cudaGetSymbolAddress(&vD1, g_nd2_1);
    cudaGetSymbolAddress(&vN2, g_nidx2);
    cudaGetSymbolAddress(&vD2, g_nd2_2);
    cudaGetSymbolAddress(&vX, g_bufX);
    cudaGetSymbolAddress(&vA, g_bufA);
    cudaGetSymbolAddress(&vB, g_bufB);
    float* aQ1 = (float*)vQ1; float* aQ2 = (float*)vQ2;
    int* aN1 = (int*)vN1; float* aD1 = (float*)vD1;
    int* aN2 = (int*)vN2; float* aD2 = (float*)vD2;
    float* aX = (float*)vX; float* aA = (float*)vA; float* aB = (float*)vB;

    // ---- SA module 1 ----
    fps_kernel<<<BATCH, 512>>>(xyz, NPTS, M1, aQ1);
    knn_kernel<<<BATCH*M1, 256, NPTS*sizeof(float)>>>(xyz, aQ1, NPTS, M1, aN1, aD1);
    gather1_kernel<<<R1/256, 256>>>(color, xyz);
    gemm_bn<<<dim3(1, R1/64), 128>>>(aX, w1a, b1a, g1a, be1a, aA, R1, 6, 64);
    gemm_bn<<<dim3(1, R1/64), 128>>>(aA, w1b, b1b, g1b, be1b, aB, R1, 64, 64);
    maxagg1_kernel<<<BATCH*M1, 64>>>();

    // ---- SA module 2 ----
    fps_kernel<<<BATCH, 512>>>(aQ1, M1, M2, aQ2);
    knn_kernel<<<BATCH*M2, 256, M1*sizeof(float)>>>(aQ1, aQ2, M1, M2, aN2, aD2);
    gather2_kernel<<<(R2*32)/256, 256>>>();
    gemm_bn<<<dim3(2, R2/64), 128>>>(aX, w2a, b2a, g2a, be2a, aA, R2, 131, 128);
    gemm_bn<<<dim3(4, R2/64), 128>>>(aA, w2b, b2b, g2b, be2b, aB, R2, 128, 256);
    maxagg2_kernel<<<BATCH*M2, 256>>>();

    // ---- mlp3 + global max + head ----
    gather3_kernel<<<(R3*515 + 255)/256, 256>>>();
    gemm_bn<<<dim3(16, (R3 + 63)/64), 128>>>(aX, w3, b3, g3, be3, aA, R3, 515, 1024);
    globalmax_kernel<<<dim3(4, BATCH), 256>>>();
    head_kernel<<<BATCH, 512>>>(wl1, bl1, wl2, bl2, out);
}

// round 9
// speedup vs baseline: 1.6745x; 1.6745x over previous
#include <cuda_runtime.h>
#include <math.h>

#define BATCH 4
#define NPTS  4096
#define M1    2048
#define M2    410
#define KNN   64
#define R1 (BATCH*M1*KNN)   /* 524288 */
#define R2 (BATCH*M2*KNN)   /* 104960 */
#define R3 (BATCH*M2)       /* 1640   */

// ---------------- static scratch (no allocations allowed) ----------------
__device__ float g_qpos1[BATCH*M1*3];
__device__ float g_qpos2[BATCH*M2*3];
__device__ int   g_nidx1[R1];
__device__ float g_nd2_1[R1];
__device__ int   g_nidx2[R2];
__device__ float g_nd2_2[R2];
__device__ float g_x1[BATCH*M1*128];
__device__ float g_x2[BATCH*M2*512];
__device__ float g_glob[BATCH*1024];
__device__ float g_bufX[13749760];   // max(R2*131, R3*515)
__device__ float g_bufA[33554432];   // max(R1*64, R2*128, R3*1024)
__device__ float g_bufB[33554432];   // max(R1*64, R2*256)

// ---------------- packed f32x2 helpers ----------------
__device__ __forceinline__ unsigned long long pack2(float lo, float hi) {
    unsigned long long r;
    asm("mov.b64 %0, {%1, %2};" : "=l"(r) : "f"(lo), "f"(hi));
    return r;
}
__device__ __forceinline__ void unpack2(unsigned long long v, float& lo, float& hi) {
    asm("mov.b64 {%0, %1}, %2;" : "=f"(lo), "=f"(hi) : "l"(v));
}
__device__ __forceinline__ unsigned long long add2(unsigned long long a, unsigned long long b) {
    unsigned long long r; asm("add.rn.f32x2 %0, %1, %2;" : "=l"(r) : "l"(a), "l"(b)); return r;
}
__device__ __forceinline__ unsigned long long mul2(unsigned long long a, unsigned long long b) {
    unsigned long long r; asm("mul.rn.f32x2 %0, %1, %2;" : "=l"(r) : "l"(a), "l"(b)); return r;
}

// =====================================================================
// Fast FPS. One block per batch, 128 threads, PTS contiguous points per
// thread, register-resident, distances in packed f32x2.
// NO dynamic smem (round-8 capture failure was static+dynamic > 48KB).
// Value argmax via redux.sync; first-index ties via monotonic atomicMax
// key (it<<12)|(4095-idx); winner coords re-read from global (L1 hit,
// same-address broadcast). Rounding order matches jnp exactly:
// dx=x+(-lx); (dx*dx+dy*dy)+dz*dz; min; argmax first-index.
// =====================================================================
template<int PTS>
__global__ void __launch_bounds__(128) fps_fast(const float* __restrict__ pos,
                                                int n, int m,
                                                float* __restrict__ qpos)
{
    constexpr int PAIRS = PTS / 2;
    __shared__ unsigned s_wv[4];
    __shared__ int s_key;

    const int b = blockIdx.x;
    const float* P = pos + (size_t)b * n * 3;
    float* Q = qpos + (size_t)b * m * 3;
    const int tid = threadIdx.x;
    const int lane = tid & 31, wid = tid >> 5;
    const int base = tid * PTS;

    // load my PTS points (contiguous) into packed registers
    unsigned long long px2[PAIRS], py2[PAIRS], pz2[PAIRS];
    float md[PTS];
#pragma unroll
    for (int j = 0; j < PAIRS; j++) {
        const float* p0 = P + (size_t)(base + 2*j) * 3;
        px2[j] = pack2(p0[0], p0[3]);
        py2[j] = pack2(p0[1], p0[4]);
        pz2[j] = pack2(p0[2], p0[5]);
    }
#pragma unroll
    for (int j = 0; j < PTS; j++) md[j] = __int_as_float(0x7f800000);

    if (tid == 0) s_key = -1;
    __syncthreads();

    float lx = P[0], ly = P[1], lz = P[2];
    if (tid == 0) { Q[0] = lx; Q[1] = ly; Q[2] = lz; }

    for (int it = 1; it < m; it++) {
        unsigned long long nlx = pack2(-lx, -lx);
        unsigned long long nly = pack2(-ly, -ly);
        unsigned long long nlz = pack2(-lz, -lz);
        float bmA = -1.f, bmB = -1.f;
#pragma unroll
        for (int j = 0; j < PAIRS; j++) {
            unsigned long long dx = add2(px2[j], nlx);
            unsigned long long dy = add2(py2[j], nly);
            unsigned long long dz = add2(pz2[j], nlz);
            unsigned long long s = add2(add2(mul2(dx,dx), mul2(dy,dy)), mul2(dz,dz));
            float lo, hi; unpack2(s, lo, hi);
            float m0 = fminf(md[2*j],   lo); md[2*j]   = m0;
            float m1 = fminf(md[2*j+1], hi); md[2*j+1] = m1;
            bmA = fmaxf(bmA, m0);
            bmB = fmaxf(bmB, m1);
        }
        float bm = fmaxf(bmA, bmB);   // >= 0 always; uint compare is monotone
        unsigned vm = __reduce_max_sync(0xffffffffu, __float_as_uint(bm));
        if (lane == 0) s_wv[wid] = vm;
        __syncthreads();
        unsigned gv = max(max(s_wv[0], s_wv[1]), max(s_wv[2], s_wv[3]));
        if (__float_as_uint(bm) == gv) {
            int loc = PTS;
#pragma unroll
            for (int j = PTS - 1; j >= 0; j--)
                if (__float_as_uint(md[j]) == gv) loc = j;   // keeps smallest j
            if (loc < PTS) atomicMax(&s_key, (it << 12) | (4095 - (base + loc)));
        }
        __syncthreads();
        int gi = 4095 - (s_key & 4095);
        const float* pw = P + (size_t)gi * 3;   // same addr per warp -> broadcast
        lx = pw[0]; ly = pw[1]; lz = pw[2];
        if (tid == 0) {
            Q[(size_t)it*3]   = lx;
            Q[(size_t)it*3+1] = ly;
            Q[(size_t)it*3+2] = lz;
        }
    }
}

// =====================================================================
// Exact 64-NN per query. One block per query, 256 threads.
// Rounds use redux.sync (min value bits, then min matched index).
// Tie-break: lower index (matches lax.top_k stable ordering).
// =====================================================================
__global__ void __launch_bounds__(256) knn_kernel(const float* __restrict__ src,
                                                  const float* __restrict__ qpos,
                                                  int n, int m,
                                                  int* __restrict__ nidx,
                                                  float* __restrict__ nd2)
{
    extern __shared__ float sd[];   // n floats (<= 16KB)
    const int bq = blockIdx.x;      // b*m + q
    const int b  = bq / m;
    const float* S = src + (size_t)b * n * 3;
    const int tid = threadIdx.x;
    const float FMAX = 3.402823466e38f;

    float qx = qpos[(size_t)bq*3], qy = qpos[(size_t)bq*3+1], qz = qpos[(size_t)bq*3+2];
    for (int i = tid; i < n; i += 256) {
        float dx = __fadd_rn(S[i*3],   -qx);
        float dy = __fadd_rn(S[i*3+1], -qy);
        float dz = __fadd_rn(S[i*3+2], -qz);
        sd[i] = __fadd_rn(__fadd_rn(__fmul_rn(dx,dx), __fmul_rn(dy,dy)),
                          __fmul_rn(dz,dz));
    }
    __syncthreads();

    float lv = FMAX; int li = 0x7fffffff;
    for (int i = tid; i < n; i += 256) { float v = sd[i]; if (v < lv) { lv = v; li = i; } }

    __shared__ unsigned swv[8];
    __shared__ unsigned swi[8];
    __shared__ int s_sel;

    for (int k = 0; k < KNN; k++) {
        unsigned lb = __float_as_uint(lv);                 // d2 >= 0: bits monotone
        unsigned vm = __reduce_min_sync(0xffffffffu, lb);
        unsigned im = __reduce_min_sync(0xffffffffu, (lb == vm) ? (unsigned)li : 0xffffffffu);
        if ((tid & 31) == 0) { swv[tid >> 5] = vm; swi[tid >> 5] = im; }
        __syncthreads();
        if (tid < 32) {
            unsigned v = (tid < 8) ? swv[tid] : 0xffffffffu;
            unsigned i = (tid < 8) ? swi[tid] : 0xffffffffu;
            unsigned vm2 = __reduce_min_sync(0xffffffffu, v);
            unsigned im2 = __reduce_min_sync(0xffffffffu, (v == vm2) ? i : 0xffffffffu);
            if (tid == 0) {
                s_sel = (int)im2;
                nidx[(size_t)bq*KNN + k] = (int)im2;
                nd2 [(size_t)bq*KNN + k] = __uint_as_float(vm2);
            }
        }
        __syncthreads();
        int sel = s_sel;
        if ((sel & 255) == tid) {          // owner of that strided slot rescans
            sd[sel] = FMAX;
            lv = FMAX; li = 0x7fffffff;
            for (int i = tid; i < n; i += 256) { float v = sd[i]; if (v < lv) { lv = v; li = i; } }
        }
    }
}

// =====================================================================
// Fused gather + SA1 first layer (K=6 -> 64) + bias + ReLU + BN.
// One thread per output element (r, n).
// =====================================================================
__global__ void __launch_bounds__(256) fused_l1a_kernel(
    const float* __restrict__ color, const float* __restrict__ xyz,
    const float* __restrict__ w, const float* __restrict__ bias,
    const float* __restrict__ gamma, const float* __restrict__ beta)
{
    int idx = blockIdx.x * 256 + threadIdx.x;   // r*64 + n
    int nn = idx & 63, r = idx >> 6;
    int b = r >> 17;                 // M1*KNN = 131072
    int q = (r >> 6) & (M1 - 1);
    int pt = g_nidx1[r];
    const float* cb = color + ((size_t)b*NPTS + pt) * 3;
    const float* pb = xyz   + ((size_t)b*NPTS + pt) * 3;
    const float* qp = g_qpos1 + ((size_t)(b*M1 + q)) * 3;
    float f0 = cb[0], f1 = cb[1], f2 = cb[2];
    float f3 = pb[0] - qp[0], f4 = pb[1] - qp[1], f5 = pb[2] - qp[2];
    float acc = 0.f;
    acc = fmaf(f0, w[nn],        acc);
    acc = fmaf(f1, w[64  + nn],  acc);
    acc = fmaf(f2, w[128 + nn],  acc);
    acc = fmaf(f3, w[192 + nn],  acc);
    acc = fmaf(f4, w[256 + nn],  acc);
    acc = fmaf(f5, w[320 + nn],  acc);
    const float bnf = 1.0f / sqrtf(1.0f + 1e-5f);
    float v = fmaxf(acc + bias[nn], 0.f);
    g_bufA[(size_t)r*64 + nn] = v * (gamma[nn] * bnf) + beta[nn];
}

// =====================================================================
// Gather kernels for SA2 / mlp3 inputs
// =====================================================================
__global__ void gather2_kernel()
{
    int gt = blockIdx.x * 256 + threadIdx.x;
    int w = gt >> 5, lane = gt & 31;
    if (w >= R2) return;
    int b = w / (M2 * KNN);
    int q = (w / KNN) % M2;
    int n = g_nidx2[w];
    const float* xr = g_x1 + ((size_t)(b*M1 + n)) * 128;
    float* o = g_bufX + (size_t)w * 131;
#pragma unroll
    for (int i = 0; i < 4; i++) o[lane + 32*i] = xr[lane + 32*i];
    if (lane < 3)
        o[128 + lane] = g_qpos1[((size_t)(b*M1 + n))*3 + lane]
                      - g_qpos2[((size_t)(b*M2 + q))*3 + lane];
}

__global__ void gather3_kernel()
{
    int e = blockIdx.x * 256 + threadIdx.x;
    if (e >= R3 * 515) return;
    int row = e / 515, c = e % 515;
    g_bufX[e] = (c < 512) ? g_x2[(size_t)row*512 + c]
                          : g_qpos2[(size_t)row*3 + (c - 512)];
}

// =====================================================================
// Tiled SGEMM Y = bn(relu(X @ W + bias)) using packed fma.rn.f32x2.
// BM=BN=64, BK=16, 128 threads, 8x4 microtile (rows packed in pairs).
// =====================================================================
#define BKK 16
__global__ void __launch_bounds__(128) gemm_bn(const float* __restrict__ X,
    const float* __restrict__ W, const float* __restrict__ bias,
    const float* __restrict__ gamma, const float* __restrict__ beta,
    float* __restrict__ Y, int M, int K, int N)
{
    __shared__ __align__(16) float As[BKK][64 + 4];
    __shared__ __align__(16) float Bs[BKK][64 + 4];
    const int tid = threadIdx.x;
    const int bm = blockIdx.y * 64, bn = blockIdx.x * 64;
    const int tn = (tid & 15) * 4;
    const int tm = (tid >> 4) * 8;

    unsigned long long acc[4][4];
#pragma unroll
    for (int i = 0; i < 4; i++)
#pragma unroll
        for (int j = 0; j < 4; j++) acc[i][j] = 0ull;

    for (int k0 = 0; k0 < K; k0 += BKK) {
#pragma unroll
        for (int i = 0; i < 8; i++) {
            int t = i*128 + tid;
            int m = t >> 4, k = t & 15;
            float v = 0.f;
            int gr = bm + m, gk = k0 + k;
            if (gr < M && gk < K) v = X[(size_t)gr*K + gk];
            As[k][m] = v;
        }
#pragma unroll
        for (int i = 0; i < 8; i++) {
            int t = i*128 + tid;
            int k = t >> 6, n = t & 63;
            float v = 0.f;
            int gk = k0 + k;
            if (gk < K) v = W[(size_t)gk*N + bn + n];
            Bs[k][n] = v;
        }
        __syncthreads();
#pragma unroll
        for (int kk = 0; kk < BKK; kk++) {
            unsigned long long a2[4], b2[4];
#pragma unroll
            for (int i = 0; i < 4; i++)
                a2[i] = *(const unsigned long long*)&As[kk][tm + 2*i];
#pragma unroll
            for (int j = 0; j < 4; j++) {
                float bv = Bs[kk][tn + j];
                asm("mov.b64 %0, {%1, %1};" : "=l"(b2[j]) : "f"(bv));
            }
#pragma unroll
            for (int i = 0; i < 4; i++)
#pragma unroll
                for (int j = 0; j < 4; j++)
                    asm("fma.rn.f32x2 %0, %1, %2, %0;"
                        : "+l"(acc[i][j]) : "l"(a2[i]), "l"(b2[j]));
        }
        __syncthreads();
    }

    const float bnf = 1.0f / sqrtf(1.0f + 1e-5f);
    float s[4], t[4], bi[4];
#pragma unroll
    for (int j = 0; j < 4; j++) {
        int c = bn + tn + j;
        s[j] = gamma[c] * bnf; t[j] = beta[c]; bi[j] = bias[c];
    }
#pragma unroll
    for (int i = 0; i < 4; i++) {
#pragma unroll
        for (int j = 0; j < 4; j++) {
            float lo, hi;
            asm("mov.b64 {%0, %1}, %2;" : "=f"(lo), "=f"(hi) : "l"(acc[i][j]));
            int r0 = bm + tm + 2*i;
            if (r0 < M) {
                float v = fmaxf(lo + bi[j], 0.f);
                Y[(size_t)r0*N + bn + tn + j] = v * s[j] + t[j];
            }
            if (r0 + 1 < M) {
                float v = fmaxf(hi + bi[j], 0.f);
                Y[(size_t)(r0+1)*N + bn + tn + j] = v * s[j] + t[j];
            }
        }
    }
}

// =====================================================================
// Masked max-aggregation over K neighbors, two radii per SA module.
// =====================================================================
__global__ void maxagg1_kernel()
{
    int bq = blockIdx.x, f = threadIdx.x;   // 64 threads
    const float rA = (float)(0.2*0.2), rB = (float)(0.1*0.1);
    float mA = -3.402823466e38f, mB = -3.402823466e38f;
    bool aA = false, aB = false;
    for (int k = 0; k < KNN; k++) {
        float d2 = g_nd2_1[(size_t)bq*KNN + k];
        float h  = g_bufB[((size_t)bq*KNN + k)*64 + f];
        if (d2 <= rA) { aA = true; mA = fmaxf(mA, h); }
        if (d2 <= rB) { aB = true; mB = fmaxf(mB, h); }
    }
    g_x1[(size_t)bq*128 + f]      = aA ? mA : 0.f;
    g_x1[(size_t)bq*128 + 64 + f] = aB ? mB : 0.f;
}

__global__ void maxagg2_kernel()
{
    int bq = blockIdx.x, f = threadIdx.x;   // 256 threads
    const float rA = (float)(0.35*0.35), rB = (float)(0.5*0.5);
    float mA = -3.402823466e38f, mB = -3.402823466e38f;
    bool aA = false, aB = false;
    for (int k = 0; k < KNN; k++) {
        float d2 = g_nd2_2[(size_t)bq*KNN + k];
        float h  = g_bufB[((size_t)bq*KNN + k)*256 + f];
        if (d2 <= rA) { aA = true; mA = fmaxf(mA, h); }
        if (d2 <= rB) { aB = true; mB = fmaxf(mB, h); }
    }
    g_x2[(size_t)bq*512 + f]       = aA ? mA : 0.f;
    g_x2[(size_t)bq*512 + 256 + f] = aB ? mB : 0.f;
}

__global__ void globalmax_kernel()
{
    int f = blockIdx.x * 256 + threadIdx.x;   // 1024 feats
    int b = blockIdx.y;
    float m = -3.402823466e38f;
    for (int q = 0; q < M2; q++)
        m = fmaxf(m, g_bufA[((size_t)(b*M2 + q))*1024 + f]);
    g_glob[(size_t)b*1024 + f] = m;
}

// =====================================================================
// Head: h1 = relu(g @ wl1 + bl1); out = h1 @ wl2 + bl2; L2-normalize.
// =====================================================================
__global__ void __launch_bounds__(512) head_kernel(
    const float* __restrict__ wl1, const float* __restrict__ bl1,
    const float* __restrict__ wl2, const float* __restrict__ bl2,
    float* __restrict__ out)
{
    __shared__ float sg[1024];
    __shared__ float sh[512];
    __shared__ float so[128];
    __shared__ float snorm;
    int b = blockIdx.x, tid = threadIdx.x;
    sg[tid]       = g_glob[(size_t)b*1024 + tid];
    sg[tid + 512] = g_glob[(size_t)b*1024 + 512 + tid];
    __syncthreads();

    float acc = bl1[tid];
    for (int k = 0; k < 1024; k++) acc = fmaf(sg[k], wl1[(size_t)k*512 + tid], acc);
    sh[tid] = fmaxf(acc, 0.f);
    __syncthreads();

    if (tid < 128) {
        float o = bl2[tid];
        for (int k = 0; k < 512; k++) o = fmaf(sh[k], wl2[(size_t)k*128 + tid], o);
        so[tid] = o;
    }
    __syncthreads();
    if (tid < 32) {
        float s = 0.f;
        for (int c = tid; c < 128; c += 32) s += so[c] * so[c];
#pragma unroll
        for (int off = 16; off > 0; off >>= 1) s += __shfl_down_sync(0xffffffffu, s, off);
        if (tid == 0) snorm = sqrtf(s);
    }
    __syncthreads();
    if (tid < 128) out[(size_t)b*128 + tid] = so[tid] / snorm;
}

// =====================================================================
extern "C" void kernel_launch(void* const* d_in, const int* in_sizes, int n_in,
                              void* d_out, int out_size)
{
    const float* xyz   = (const float*)d_in[0];
    const float* color = (const float*)d_in[1];
    const float* w1a = (const float*)d_in[2],  *b1a = (const float*)d_in[3];
    const float* g1a = (const float*)d_in[4],  *be1a = (const float*)d_in[5];
    const float* w1b = (const float*)d_in[6],  *b1b = (const float*)d_in[7];
    const float* g1b = (const float*)d_in[8],  *be1b = (const float*)d_in[9];
    const float* w2a = (const float*)d_in[10], *b2a = (const float*)d_in[11];
    const float* g2a = (const float*)d_in[12], *be2a = (const float*)d_in[13];
    const float* w2b = (const float*)d_in[14], *b2b = (const float*)d_in[15];
    const float* g2b = (const float*)d_in[16], *be2b = (const float*)d_in[17];
    const float* w3  = (const float*)d_in[18], *b3  = (const float*)d_in[19];
    const float* g3  = (const float*)d_in[20], *be3 = (const float*)d_in[21];
    const float* wl1 = (const float*)d_in[22], *bl1 = (const float*)d_in[23];
    const float* wl2 = (const float*)d_in[24], *bl2 = (const float*)d_in[25];
    float* out = (float*)d_out;

    void *vQ1, *vQ2, *vN1, *vD1, *vN2, *vD2, *vX, *vA, *vB;
    cudaGetSymbolAddress(&vQ1, g_qpos1);
    cudaGetSymbolAddress(&vQ2, g_qpos2);
    cudaGetSymbolAddress(&vN1, g_nidx1);
    cudaGetSymbolAddress(&vD1, g_nd2_1);
    cudaGetSymbolAddress(&vN2, g_nidx2);
    cudaGetSymbolAddress(&vD2, g_nd2_2);
    cudaGetSymbolAddress(&vX, g_bufX);
    cudaGetSymbolAddress(&vA, g_bufA);
    cudaGetSymbolAddress(&vB, g_bufB);
    float* aQ1 = (float*)vQ1; float* aQ2 = (float*)vQ2;
    int* aN1 = (int*)vN1; float* aD1 = (float*)vD1;
    int* aN2 = (int*)vN2; float* aD2 = (float*)vD2;
    float* aX = (float*)vX; float* aA = (float*)vA; float* aB = (float*)vB;

    // ---- SA module 1 ----
    fps_fast<32><<<BATCH, 128>>>(xyz, NPTS, M1, aQ1);
    knn_kernel<<<BATCH*M1, 256, NPTS*sizeof(float)>>>(xyz, aQ1, NPTS, M1, aN1, aD1);
    fused_l1a_kernel<<<(R1*64)/256, 256>>>(color, xyz, w1a, b1a, g1a, be1a);
    gemm_bn<<<dim3(1, R1/64), 128>>>(aA, w1b, b1b, g1b, be1b, aB, R1, 64, 64);
    maxagg1_kernel<<<BATCH*M1, 64>>>();

    // ---- SA module 2 ----
    fps_fast<16><<<BATCH, 128>>>(aQ1, M1, M2, aQ2);
    knn_kernel<<<BATCH*M2, 256, M1*sizeof(float)>>>(aQ1, aQ2, M1, M2, aN2, aD2);
    gather2_kernel<<<(R2*32)/256, 256>>>();
    gemm_bn<<<dim3(2, R2/64), 128>>>(aX, w2a, b2a, g2a, be2a, aA, R2, 131, 128);
    gemm_bn<<<dim3(4, R2/64), 128>>>(aA, w2b, b2b, g2b, be2b, aB, R2, 128, 256);
    maxagg2_kernel<<<BATCH*M2, 256>>>();

    // ---- mlp3 + global max + head ----
    gather3_kernel<<<(R3*515 + 255)/256, 256>>>();
    gemm_bn<<<dim3(16, (R3 + 63)/64), 128>>>(aX, w3, b3, g3, be3, aA, R3, 515, 1024);
    globalmax_kernel<<<dim3(4, BATCH), 256>>>();
    head_kernel<<<BATCH, 512>>>(wl1, bl1, wl2, bl2, out);
}

// round 10
// speedup vs baseline: 2.0533x; 1.2263x over previous
#include <cuda_runtime.h>
#include <math.h>

#define BATCH 4
#define NPTS  4096
#define M1    2048
#define M2    410
#define KNN   64
#define R1 (BATCH*M1*KNN)   /* 524288 */
#define R2 (BATCH*M2*KNN)   /* 104960 */
#define R3 (BATCH*M2)       /* 1640   */

// ---------------- static scratch (no allocations allowed) ----------------
__device__ float g_qpos1[BATCH*M1*3];
__device__ float g_qpos2[BATCH*M2*3];
__device__ int   g_nidx1[R1];
__device__ float g_nd2_1[R1];
__device__ int   g_nidx2[R2];
__device__ float g_nd2_2[R2];
__device__ float g_x1[BATCH*M1*128];
__device__ float g_x2[BATCH*M2*512];
__device__ float g_glob[BATCH*1024];
__device__ float g_bufX[13749760];   // max(R2*131, R3*515)
__device__ float g_bufA[13762560];   // max(R2*128, R3*1024)

// ---------------- packed f32x2 helpers ----------------
__device__ __forceinline__ unsigned long long pack2(float lo, float hi) {
    unsigned long long r;
    asm("mov.b64 %0, {%1, %2};" : "=l"(r) : "f"(lo), "f"(hi));
    return r;
}
__device__ __forceinline__ void unpack2(unsigned long long v, float& lo, float& hi) {
    asm("mov.b64 {%0, %1}, %2;" : "=f"(lo), "=f"(hi) : "l"(v));
}
__device__ __forceinline__ unsigned long long add2(unsigned long long a, unsigned long long b) {
    unsigned long long r; asm("add.rn.f32x2 %0, %1, %2;" : "=l"(r) : "l"(a), "l"(b)); return r;
}
__device__ __forceinline__ unsigned long long mul2(unsigned long long a, unsigned long long b) {
    unsigned long long r; asm("mul.rn.f32x2 %0, %1, %2;" : "=l"(r) : "l"(a), "l"(b)); return r;
}

// =====================================================================
// Fast FPS (unchanged from round 9 — passing). One block per batch,
// 128 threads, PTS contiguous points per thread in packed f32x2 regs.
// =====================================================================
template<int PTS>
__global__ void __launch_bounds__(128) fps_fast(const float* __restrict__ pos,
                                                int n, int m,
                                                float* __restrict__ qpos)
{
    constexpr int PAIRS = PTS / 2;
    __shared__ unsigned s_wv[4];
    __shared__ int s_key;

    const int b = blockIdx.x;
    const float* P = pos + (size_t)b * n * 3;
    float* Q = qpos + (size_t)b * m * 3;
    const int tid = threadIdx.x;
    const int lane = tid & 31, wid = tid >> 5;
    const int base = tid * PTS;

    unsigned long long px2[PAIRS], py2[PAIRS], pz2[PAIRS];
    float md[PTS];
#pragma unroll
    for (int j = 0; j < PAIRS; j++) {
        const float* p0 = P + (size_t)(base + 2*j) * 3;
        px2[j] = pack2(p0[0], p0[3]);
        py2[j] = pack2(p0[1], p0[4]);
        pz2[j] = pack2(p0[2], p0[5]);
    }
#pragma unroll
    for (int j = 0; j < PTS; j++) md[j] = __int_as_float(0x7f800000);

    if (tid == 0) s_key = -1;
    __syncthreads();

    float lx = P[0], ly = P[1], lz = P[2];
    if (tid == 0) { Q[0] = lx; Q[1] = ly; Q[2] = lz; }

    for (int it = 1; it < m; it++) {
        unsigned long long nlx = pack2(-lx, -lx);
        unsigned long long nly = pack2(-ly, -ly);
        unsigned long long nlz = pack2(-lz, -lz);
        float bmA = -1.f, bmB = -1.f;
#pragma unroll
        for (int j = 0; j < PAIRS; j++) {
            unsigned long long dx = add2(px2[j], nlx);
            unsigned long long dy = add2(py2[j], nly);
            unsigned long long dz = add2(pz2[j], nlz);
            unsigned long long s = add2(add2(mul2(dx,dx), mul2(dy,dy)), mul2(dz,dz));
            float lo, hi; unpack2(s, lo, hi);
            float m0 = fminf(md[2*j],   lo); md[2*j]   = m0;
            float m1 = fminf(md[2*j+1], hi); md[2*j+1] = m1;
            bmA = fmaxf(bmA, m0);
            bmB = fmaxf(bmB, m1);
        }
        float bm = fmaxf(bmA, bmB);
        unsigned vm = __reduce_max_sync(0xffffffffu, __float_as_uint(bm));
        if (lane == 0) s_wv[wid] = vm;
        __syncthreads();
        unsigned gv = max(max(s_wv[0], s_wv[1]), max(s_wv[2], s_wv[3]));
        if (__float_as_uint(bm) == gv) {
            int loc = PTS;
#pragma unroll
            for (int j = PTS - 1; j >= 0; j--)
                if (__float_as_uint(md[j]) == gv) loc = j;
            if (loc < PTS) atomicMax(&s_key, (it << 12) | (4095 - (base + loc)));
        }
        __syncthreads();
        int gi = 4095 - (s_key & 4095);
        const float* pw = P + (size_t)gi * 3;
        lx = pw[0]; ly = pw[1]; lz = pw[2];
        if (tid == 0) {
            Q[(size_t)it*3]   = lx;
            Q[(size_t)it*3+1] = ly;
            Q[(size_t)it*3+2] = lz;
        }
    }
}

// =====================================================================
// Exact 64-NN SET per query via 4-pass radix select on d2 float bits.
// Output order is ARBITRARY (downstream max/any are order-invariant);
// the SET matches lax.top_k exactly: all d2 < T, plus the smallest-index
// ties at d2 == T to fill 64 (T = exact 64th smallest, bits monotone).
// 256 threads, EPT elements per thread held in registers.
// =====================================================================
template<int EPT>
__global__ void __launch_bounds__(256) knn_select(const float* __restrict__ src,
                                                  const float* __restrict__ qpos,
                                                  int m,
                                                  int* __restrict__ nidx,
                                                  float* __restrict__ nd2)
{
    __shared__ unsigned bins[256];
    __shared__ unsigned s_b, s_r;
    __shared__ int s_cnt;
    __shared__ int s_last;
    __shared__ unsigned s_min;

    const int n = EPT * 256;
    const int bq = blockIdx.x;
    const int b  = bq / m;
    const float* S = src + (size_t)b * n * 3;
    const int tid = threadIdx.x;

    float qx = qpos[(size_t)bq*3], qy = qpos[(size_t)bq*3+1], qz = qpos[(size_t)bq*3+2];
    unsigned rb[EPT];
#pragma unroll
    for (int j = 0; j < EPT; j++) {
        int i = j*256 + tid;
        float dx = __fadd_rn(S[i*3],   -qx);
        float dy = __fadd_rn(S[i*3+1], -qy);
        float dz = __fadd_rn(S[i*3+2], -qz);
        rb[j] = __float_as_uint(__fadd_rn(__fadd_rn(__fmul_rn(dx,dx), __fmul_rn(dy,dy)),
                                          __fmul_rn(dz,dz)));
    }

    unsigned prefix = 0;
    unsigned rank = 64;
#pragma unroll
    for (int pass = 0; pass < 4; pass++) {
        const int shift = 24 - 8*pass;
        bins[tid] = 0;
        __syncthreads();
#pragma unroll
        for (int j = 0; j < EPT; j++) {
            unsigned v = rb[j];
            bool in = (pass == 0) ? true : ((v >> (shift + 8)) == prefix);
            if (in) atomicAdd(&bins[(v >> shift) & 255], 1u);
        }
        __syncthreads();
        if (tid < 32) {
            unsigned c[8]; unsigned ssum = 0;
#pragma unroll
            for (int t = 0; t < 8; t++) { c[t] = bins[tid*8 + t]; ssum += c[t]; }
            unsigned cum = ssum;
#pragma unroll
            for (int off = 1; off < 32; off <<= 1) {
                unsigned o = __shfl_up_sync(0xffffffffu, cum, off);
                if (tid >= off) cum += o;
            }
            unsigned excl = cum - ssum;
            if (rank > excl && rank <= cum) {
                unsigned rr = rank - excl;
#pragma unroll
                for (int t = 0; t < 8; t++) {
                    if (rr <= c[t]) { s_b = (unsigned)(tid*8 + t); s_r = rr; break; }
                    rr -= c[t];
                }
            }
        }
        __syncthreads();
        prefix = (prefix << 8) | s_b;
        rank = s_r;
        __syncthreads();
    }

    const unsigned T = prefix;        // 64th smallest value (bits)
    const int take = (int)rank;       // ties at T to take (>=1)

    if (tid == 0) { s_cnt = 0; s_last = -1; }
    __syncthreads();
    // emit all strictly-less elements, arbitrary slot order
#pragma unroll
    for (int j = 0; j < EPT; j++) {
        if (rb[j] < T) {
            int slot = atomicAdd(&s_cnt, 1);
            int i = j*256 + tid;
            nidx[(size_t)bq*KNN + slot] = i;
            nd2 [(size_t)bq*KNN + slot] = __uint_as_float(rb[j]);
        }
    }
    __syncthreads();
    const int c_less = s_cnt;         // == 64 - take
    // ties: smallest indices first
    for (int t = 0; t < take; t++) {
        if (tid == 0) s_min = 0xffffffffu;
        __syncthreads();
        int last = s_last;
#pragma unroll
        for (int j = 0; j < EPT; j++) {
            int i = j*256 + tid;
            if (rb[j] == T && i > last) atomicMin(&s_min, (unsigned)i);
        }
        __syncthreads();
        if (tid == 0) {
            int win = (int)s_min;
            s_last = win;
            nidx[(size_t)bq*KNN + c_less + t] = win;
            nd2 [(size_t)bq*KNN + c_less + t] = __uint_as_float(T);
        }
        __syncthreads();
    }
}

// =====================================================================
// Fully fused SA1 PointConv per query: gather(6) -> Lin6x64+ReLU+BN ->
// Lin64x64+ReLU+BN -> dual-radius masked max -> g_x1[bq][128].
// One block (128 threads) per query; everything in shared memory.
// =====================================================================
__global__ void __launch_bounds__(128) sa1_fused(
    const float* __restrict__ color, const float* __restrict__ xyz,
    const float* __restrict__ w1a, const float* __restrict__ b1a,
    const float* __restrict__ g1a, const float* __restrict__ be1a,
    const float* __restrict__ w1b, const float* __restrict__ b1b,
    const float* __restrict__ g1b, const float* __restrict__ be1b)
{
    __shared__ __align__(16) float feats[64][6];
    __shared__ __align__(16) float Xs[64][66];   // [feature k][row]
    __shared__ __align__(16) float Ws[64][66];   // w1b [k][n]
    __shared__ float d2s[64];
    __shared__ float redA[8][64];
    __shared__ float redB[8][64];

    const int bq = blockIdx.x;
    const int tid = threadIdx.x;
    const float bnf = 1.0f / sqrtf(1.0f + 1e-5f);

    // gather neighbor features + d2
    if (tid < 64) {
        int r = bq*KNN + tid;
        int pt = g_nidx1[r];
        d2s[tid] = g_nd2_1[r];
        int b = bq >> 11;                 // bq = b*M1 + q
        const float* cb = color + ((size_t)b*NPTS + pt) * 3;
        const float* pb = xyz   + ((size_t)b*NPTS + pt) * 3;
        const float* qp = g_qpos1 + (size_t)bq * 3;
        feats[tid][0] = cb[0]; feats[tid][1] = cb[1]; feats[tid][2] = cb[2];
        feats[tid][3] = pb[0] - qp[0];
        feats[tid][4] = pb[1] - qp[1];
        feats[tid][5] = pb[2] - qp[2];
    }
    // stage w1b into smem
    for (int i = tid; i < 4096; i += 128) Ws[i >> 6][i & 63] = w1b[i];
    __syncthreads();

    // layer 1: each thread computes 32 outputs (row = tid>>1, half of cols)
    {
        int row = tid >> 1;
        int cb0 = (tid & 1) * 32;
        float f0 = feats[row][0], f1 = feats[row][1], f2 = feats[row][2];
        float f3 = feats[row][3], f4 = feats[row][4], f5 = feats[row][5];
#pragma unroll 8
        for (int c = 0; c < 32; c++) {
            int col = cb0 + c;
            float acc = 0.f;
            acc = fmaf(f0, w1a[col],        acc);
            acc = fmaf(f1, w1a[64  + col],  acc);
            acc = fmaf(f2, w1a[128 + col],  acc);
            acc = fmaf(f3, w1a[192 + col],  acc);
            acc = fmaf(f4, w1a[256 + col],  acc);
            acc = fmaf(f5, w1a[320 + col],  acc);
            float v = fmaxf(acc + b1a[col], 0.f);
            Xs[col][row] = v * (g1a[col] * bnf) + be1a[col];
        }
    }
    __syncthreads();

    // layer 2: 64x64 @ 64x64 microtile (rows paired in f32x2)
    const int tn = (tid & 15) * 4;
    const int tm = (tid >> 4) * 8;
    unsigned long long acc[4][4];
#pragma unroll
    for (int i = 0; i < 4; i++)
#pragma unroll
        for (int j = 0; j < 4; j++) acc[i][j] = 0ull;

#pragma unroll 4
    for (int k = 0; k < 64; k++) {
        unsigned long long a2[4], b2[4];
#pragma unroll
        for (int i = 0; i < 4; i++)
            a2[i] = *(const unsigned long long*)&Xs[k][tm + 2*i];
#pragma unroll
        for (int j = 0; j < 4; j++) {
            float bv = Ws[k][tn + j];
            asm("mov.b64 %0, {%1, %1};" : "=l"(b2[j]) : "f"(bv));
        }
#pragma unroll
        for (int i = 0; i < 4; i++)
#pragma unroll
            for (int j = 0; j < 4; j++)
                asm("fma.rn.f32x2 %0, %1, %2, %0;"
                    : "+l"(acc[i][j]) : "l"(a2[i]), "l"(b2[j]));
    }

    // epilogue: bias/relu/bn + masked max over this thread's 8 rows
    const float rA = (float)(0.2*0.2), rB = (float)(0.1*0.1);
    const float NEG = -3.402823466e38f;
#pragma unroll
    for (int j = 0; j < 4; j++) {
        int col = tn + j;
        float s = g1b[col] * bnf, t = be1b[col], bi = b1b[col];
        float mA = NEG, mB = NEG;
#pragma unroll
        for (int i = 0; i < 4; i++) {
            float lo, hi; unpack2(acc[i][j], lo, hi);
            int r0 = tm + 2*i;
            float vlo = fmaxf(lo + bi, 0.f) * s + t;
            float vhi = fmaxf(hi + bi, 0.f) * s + t;
            float dA = d2s[r0], dB = d2s[r0+1];
            if (dA <= rA) mA = fmaxf(mA, vlo);
            if (dA <= rB) mB = fmaxf(mB, vlo);
            if (dB <= rA) mA = fmaxf(mA, vhi);
            if (dB <= rB) mB = fmaxf(mB, vhi);
        }
        redA[tid >> 4][col] = mA;
        redB[tid >> 4][col] = mB;
    }
    __syncthreads();
    if (tid < 64) {
        float a = NEG, c = NEG;
#pragma unroll
        for (int g = 0; g < 8; g++) {
            a = fmaxf(a, redA[g][tid]);
            c = fmaxf(c, redB[g][tid]);
        }
        g_x1[(size_t)bq*128 + tid]      = (a > -1e30f) ? a : 0.f;
        g_x1[(size_t)bq*128 + 64 + tid] = (c > -1e30f) ? c : 0.f;
    }
}

// =====================================================================
// Gather kernels for SA2 / mlp3 inputs
// =====================================================================
__global__ void gather2_kernel()
{
    int gt = blockIdx.x * 256 + threadIdx.x;
    int w = gt >> 5, lane = gt & 31;
    if (w >= R2) return;
    int b = w / (M2 * KNN);
    int q = (w / KNN) % M2;
    int n = g_nidx2[w];
    const float* xr = g_x1 + ((size_t)(b*M1 + n)) * 128;
    float* o = g_bufX + (size_t)w * 131;
#pragma unroll
    for (int i = 0; i < 4; i++) o[lane + 32*i] = xr[lane + 32*i];
    if (lane < 3)
        o[128 + lane] = g_qpos1[((size_t)(b*M1 + n))*3 + lane]
                      - g_qpos2[((size_t)(b*M2 + q))*3 + lane];
}

__global__ void gather3_kernel()
{
    int e = blockIdx.x * 256 + threadIdx.x;
    if (e >= R3 * 515) return;
    int row = e / 515, c = e % 515;
    g_bufX[e] = (c < 512) ? g_x2[(size_t)row*512 + c]
                          : g_qpos2[(size_t)row*3 + (c - 512)];
}

// =====================================================================
// Tiled SGEMM Y = bn(relu(X @ W + bias)) with packed fma.rn.f32x2.
// BM=BN=64, BK=16, 128 threads, 8x4 microtile (rows paired).
// =====================================================================
#define BKK 16
__global__ void __launch_bounds__(128) gemm_bn(const float* __restrict__ X,
    const float* __restrict__ W, const float* __restrict__ bias,
    const float* __restrict__ gamma, const float* __restrict__ beta,
    float* __restrict__ Y, int M, int K, int N)
{
    __shared__ __align__(16) float As[BKK][64 + 4];
    __shared__ __align__(16) float Bs[BKK][64 + 4];
    const int tid = threadIdx.x;
    const int bm = blockIdx.y * 64, bn = blockIdx.x * 64;
    const int tn = (tid & 15) * 4;
    const int tm = (tid >> 4) * 8;

    unsigned long long acc[4][4];
#pragma unroll
    for (int i = 0; i < 4; i++)
#pragma unroll
        for (int j = 0; j < 4; j++) acc[i][j] = 0ull;

    for (int k0 = 0; k0 < K; k0 += BKK) {
#pragma unroll
        for (int i = 0; i < 8; i++) {
            int t = i*128 + tid;
            int m = t >> 4, k = t & 15;
            float v = 0.f;
            int gr = bm + m, gk = k0 + k;
            if (gr < M && gk < K) v = X[(size_t)gr*K + gk];
            As[k][m] = v;
        }
#pragma unroll
        for (int i = 0; i < 8; i++) {
            int t = i*128 + tid;
            int k = t >> 6, n = t & 63;
            float v = 0.f;
            int gk = k0 + k;
            if (gk < K) v = W[(size_t)gk*N + bn + n];
            Bs[k][n] = v;
        }
        __syncthreads();
#pragma unroll
        for (int kk = 0; kk < BKK; kk++) {
            unsigned long long a2[4], b2[4];
#pragma unroll
            for (int i = 0; i < 4; i++)
                a2[i] = *(const unsigned long long*)&As[kk][tm + 2*i];
#pragma unroll
            for (int j = 0; j < 4; j++) {
                float bv = Bs[kk][tn + j];
                asm("mov.b64 %0, {%1, %1};" : "=l"(b2[j]) : "f"(bv));
            }
#pragma unroll
            for (int i = 0; i < 4; i++)
#pragma unroll
                for (int j = 0; j < 4; j++)
                    asm("fma.rn.f32x2 %0, %1, %2, %0;"
                        : "+l"(acc[i][j]) : "l"(a2[i]), "l"(b2[j]));
        }
        __syncthreads();
    }

    const float bnf = 1.0f / sqrtf(1.0f + 1e-5f);
    float s[4], t[4], bi[4];
#pragma unroll
    for (int j = 0; j < 4; j++) {
        int c = bn + tn + j;
        s[j] = gamma[c] * bnf; t[j] = beta[c]; bi[j] = bias[c];
    }
#pragma unroll
    for (int i = 0; i < 4; i++) {
#pragma unroll
        for (int j = 0; j < 4; j++) {
            float lo, hi; unpack2(acc[i][j], lo, hi);
            int r0 = bm + tm + 2*i;
            if (r0 < M) {
                float v = fmaxf(lo + bi[j], 0.f);
                Y[(size_t)r0*N + bn + tn + j] = v * s[j] + t[j];
            }
            if (r0 + 1 < M) {
                float v = fmaxf(hi + bi[j], 0.f);
                Y[(size_t)(r0+1)*N + bn + tn + j] = v * s[j] + t[j];
            }
        }
    }
}

// =====================================================================
// SA2 layer-2 GEMM (K=128, N=256) with FUSED dual-radius masked max.
// Each block = one query's 64 rows x 64 of the 256 cols.
// Writes g_x2[bq][radius*256 + col].
// =====================================================================
__global__ void __launch_bounds__(128) gemm_bn_max2(const float* __restrict__ X,
    const float* __restrict__ W, const float* __restrict__ bias,
    const float* __restrict__ gamma, const float* __restrict__ beta)
{
    __shared__ __align__(16) float As[BKK][64 + 4];
    __shared__ __align__(16) float Bs[BKK][64 + 4];
    __shared__ float d2s[64];
    __shared__ float redA[8][64];
    __shared__ float redB[8][64];
    const int K = 128, N = 256;
    const int tid = threadIdx.x;
    const int bq = blockIdx.y;
    const int bm = bq * 64, bn = blockIdx.x * 64;
    const int tn = (tid & 15) * 4;
    const int tm = (tid >> 4) * 8;

    if (tid < 64) d2s[tid] = g_nd2_2[(size_t)bq*KNN + tid];

    unsigned long long acc[4][4];
#pragma unroll
    for (int i = 0; i < 4; i++)
#pragma unroll
        for (int j = 0; j < 4; j++) acc[i][j] = 0ull;

    for (int k0 = 0; k0 < K; k0 += BKK) {
#pragma unroll
        for (int i = 0; i < 8; i++) {
            int t = i*128 + tid;
            int m = t >> 4, k = t & 15;
            As[k][m] = X[(size_t)(bm + m)*K + k0 + k];
        }
#pragma unroll
        for (int i = 0; i < 8; i++) {
            int t = i*128 + tid;
            int k = t >> 6, n = t & 63;
            Bs[k][n] = W[(size_t)(k0 + k)*N + bn + n];
        }
        __syncthreads();
#pragma unroll
        for (int kk = 0; kk < BKK; kk++) {
            unsigned long long a2[4], b2[4];
#pragma unroll
            for (int i = 0; i < 4; i++)
                a2[i] = *(const unsigned long long*)&As[kk][tm + 2*i];
#pragma unroll
            for (int j = 0; j < 4; j++) {
                float bv = Bs[kk][tn + j];
                asm("mov.b64 %0, {%1, %1};" : "=l"(b2[j]) : "f"(bv));
            }
#pragma unroll
            for (int i = 0; i < 4; i++)
#pragma unroll
                for (int j = 0; j < 4; j++)
                    asm("fma.rn.f32x2 %0, %1, %2, %0;"
                        : "+l"(acc[i][j]) : "l"(a2[i]), "l"(b2[j]));
        }
        __syncthreads();
    }

    const float bnf = 1.0f / sqrtf(1.0f + 1e-5f);
    const float rA = (float)(0.35*0.35), rB = (float)(0.5*0.5);
    const float NEG = -3.402823466e38f;
#pragma unroll
    for (int j = 0; j < 4; j++) {
        int c = bn + tn + j;
        float s = gamma[c] * bnf, t = beta[c], bi = bias[c];
        float mA = NEG, mB = NEG;
#pragma unroll
        for (int i = 0; i < 4; i++) {
            float lo, hi; unpack2(acc[i][j], lo, hi);
            int r0 = tm + 2*i;
            float vlo = fmaxf(lo + bi, 0.f) * s + t;
            float vhi = fmaxf(hi + bi, 0.f) * s + t;
            float dA = d2s[r0], dB = d2s[r0+1];
            if (dA <= rA) mA = fmaxf(mA, vlo);
            if (dA <= rB) mB = fmaxf(mB, vlo);
            if (dB <= rA) mA = fmaxf(mA, vhi);
            if (dB <= rB) mB = fmaxf(mB, vhi);
        }
        redA[tid >> 4][tn + j] = mA;
        redB[tid >> 4][tn + j] = mB;
    }
    __syncthreads();
    if (tid < 64) {
        float a = NEG, c = NEG;
#pragma unroll
        for (int g = 0; g < 8; g++) {
            a = fmaxf(a, redA[g][tid]);
            c = fmaxf(c, redB[g][tid]);
        }
        g_x2[(size_t)bq*512 + bn + tid]       = (a > -1e30f) ? a : 0.f;
        g_x2[(size_t)bq*512 + 256 + bn + tid] = (c > -1e30f) ? c : 0.f;
    }
}

__global__ void globalmax_kernel()
{
    int f = blockIdx.x * 256 + threadIdx.x;   // 1024 feats
    int b = blockIdx.y;
    float m = -3.402823466e38f;
    for (int q = 0; q < M2; q++)
        m = fmaxf(m, g_bufA[((size_t)(b*M2 + q))*1024 + f]);
    g_glob[(size_t)b*1024 + f] = m;
}

// =====================================================================
// Head: h1 = relu(g @ wl1 + bl1); out = h1 @ wl2 + bl2; L2-normalize.
// =====================================================================
__global__ void __launch_bounds__(512) head_kernel(
    const float* __restrict__ wl1, const float* __restrict__ bl1,
    const float* __restrict__ wl2, const float* __restrict__ bl2,
    float* __restrict__ out)
{
    __shared__ float sg[1024];
    __shared__ float sh[512];
    __shared__ float so[128];
    __shared__ float snorm;
    int b = blockIdx.x, tid = threadIdx.x;
    sg[tid]       = g_glob[(size_t)b*1024 + tid];
    sg[tid + 512] = g_glob[(size_t)b*1024 + 512 + tid];
    __syncthreads();

    float acc = bl1[tid];
    for (int k = 0; k < 1024; k++) acc = fmaf(sg[k], wl1[(size_t)k*512 + tid], acc);
    sh[tid] = fmaxf(acc, 0.f);
    __syncthreads();

    if (tid < 128) {
        float o = bl2[tid];
        for (int k = 0; k < 512; k++) o = fmaf(sh[k], wl2[(size_t)k*128 + tid], o);
        so[tid] = o;
    }
    __syncthreads();
    if (tid < 32) {
        float s = 0.f;
        for (int c = tid; c < 128; c += 32) s += so[c] * so[c];
#pragma unroll
        for (int off = 16; off > 0; off >>= 1) s += __shfl_down_sync(0xffffffffu, s, off);
        if (tid == 0) snorm = sqrtf(s);
    }
    __syncthreads();
    if (tid < 128) out[(size_t)b*128 + tid] = so[tid] / snorm;
}

// =====================================================================
extern "C" void kernel_launch(void* const* d_in, const int* in_sizes, int n_in,
                              void* d_out, int out_size)
{
    const float* xyz   = (const float*)d_in[0];
    const float* color = (const float*)d_in[1];
    const float* w1a = (const float*)d_in[2],  *b1a = (const float*)d_in[3];
    const float* g1a = (const float*)d_in[4],  *be1a = (const float*)d_in[5];
    const float* w1b = (const float*)d_in[6],  *b1b = (const float*)d_in[7];
    const float* g1b = (const float*)d_in[8],  *be1b = (const float*)d_in[9];
    const float* w2a = (const float*)d_in[10], *b2a = (const float*)d_in[11];
    const float* g2a = (const float*)d_in[12], *be2a = (const float*)d_in[13];
    const float* w2b = (const float*)d_in[14], *b2b = (const float*)d_in[15];
    const float* g2b = (const float*)d_in[16], *be2b = (const float*)d_in[17];
    const float* w3  = (const float*)d_in[18], *b3  = (const float*)d_in[19];
    const float* g3  = (const float*)d_in[20], *be3 = (const float*)d_in[21];
    const float* wl1 = (const float*)d_in[22], *bl1 = (const float*)d_in[23];
    const float* wl2 = (const float*)d_in[24], *bl2 = (const float*)d_in[25];
    float* out = (float*)d_out;

    void *vQ1, *vQ2, *vN1, *vD1, *vN2, *vD2, *vX, *vA;
    cudaGetSymbolAddress(&vQ1, g_qpos1);
    cudaGetSymbolAddress(&vQ2, g_qpos2);
    cudaGetSymbolAddress(&vN1, g_nidx1);
    cudaGetSymbolAddress(&vD1, g_nd2_1);
    cudaGetSymbolAddress(&vN2, g_nidx2);
    cudaGetSymbolAddress(&vD2, g_nd2_2);
    cudaGetSymbolAddress(&vX, g_bufX);
    cudaGetSymbolAddress(&vA, g_bufA);
    float* aQ1 = (float*)vQ1; float* aQ2 = (float*)vQ2;
    int* aN1 = (int*)vN1; float* aD1 = (float*)vD1;
    int* aN2 = (int*)vN2; float* aD2 = (float*)vD2;
    float* aX = (float*)vX; float* aA = (float*)vA;

    // ---- SA module 1 (fully fused conv) ----
    fps_fast<32><<<BATCH, 128>>>(xyz, NPTS, M1, aQ1);
    knn_select<16><<<BATCH*M1, 256>>>(xyz, aQ1, M1, aN1, aD1);
    sa1_fused<<<BATCH*M1, 128>>>(color, xyz, w1a, b1a, g1a, be1a,
                                 w1b, b1b, g1b, be1b);

    // ---- SA module 2 ----
    fps_fast<16><<<BATCH, 128>>>(aQ1, M1, M2, aQ2);
    knn_select<8><<<BATCH*M2, 256>>>(aQ1, aQ2, M2, aN2, aD2);
    gather2_kernel<<<(R2*32)/256, 256>>>();
    gemm_bn<<<dim3(2, R2/64), 128>>>(aX, w2a, b2a, g2a, be2a, aA, R2, 131, 128);
    gemm_bn_max2<<<dim3(4, R2/64), 128>>>(aA, w2b, b2b, g2b, be2b);

    // ---- mlp3 + global max + head ----
    gather3_kernel<<<(R3*515 + 255)/256, 256>>>();
    gemm_bn<<<dim3(16, (R3 + 63)/64), 128>>>(aX, w3, b3, g3, be3, aA, R3, 515, 1024);
    globalmax_kernel<<<dim3(4, BATCH), 256>>>();
    head_kernel<<<BATCH, 512>>>(wl1, bl1, wl2, bl2, out);
}

// round 11
// speedup vs baseline: 2.0963x; 1.0209x over previous
#include <cuda_runtime.h>
#include <math.h>

#define BATCH 4
#define NPTS  4096
#define M1    2048
#define M2    410
#define KNN   64
#define R1 (BATCH*M1*KNN)   /* 524288 */
#define R2 (BATCH*M2*KNN)   /* 104960 */
#define R3 (BATCH*M2)       /* 1640   */

// ---------------- static scratch (no allocations allowed) ----------------
__device__ float g_qpos1[BATCH*M1*3];
__device__ float g_qpos2[BATCH*M2*3];
__device__ int   g_nidx1[R1];
__device__ float g_nd2_1[R1];
__device__ int   g_nidx2[R2];
__device__ float g_nd2_2[R2];
__device__ float g_x1[BATCH*M1*128];
__device__ float g_x2[BATCH*M2*512];
__device__ float g_glob[BATCH*1024];
__device__ float g_bufX[13749760];   // max(R2*131, R3*515)
__device__ float g_bufA[13762560];   // max(R2*128, R3*1024)

// ---------------- packed f32x2 helpers ----------------
__device__ __forceinline__ unsigned long long pack2(float lo, float hi) {
    unsigned long long r;
    asm("mov.b64 %0, {%1, %2};" : "=l"(r) : "f"(lo), "f"(hi));
    return r;
}
__device__ __forceinline__ void unpack2(unsigned long long v, float& lo, float& hi) {
    asm("mov.b64 {%0, %1}, %2;" : "=f"(lo), "=f"(hi) : "l"(v));
}
__device__ __forceinline__ unsigned long long add2(unsigned long long a, unsigned long long b) {
    unsigned long long r; asm("add.rn.f32x2 %0, %1, %2;" : "=l"(r) : "l"(a), "l"(b)); return r;
}
__device__ __forceinline__ unsigned long long mul2(unsigned long long a, unsigned long long b) {
    unsigned long long r; asm("mul.rn.f32x2 %0, %1, %2;" : "=l"(r) : "l"(a), "l"(b)); return r;
}

// =====================================================================
// Fast FPS. One block per batch, 256 threads (8 warps), PTS contiguous
// points per thread in packed f32x2 registers. 256 threads halves the
// per-iteration compute term vs round-10's 128 threads; the serial
// reduction chain (redux -> STS -> bar -> max -> rescan -> atomic ->
// bar -> broadcast LDG) is unchanged. Semantics identical to jnp:
// dists init +inf; dx=x+(-lx); (dx*dx+dy*dy)+dz*dz; min; argmax with
// first-index ties via monotonic key (it<<12)|(4095-idx).
// =====================================================================
template<int PTS>
__global__ void __launch_bounds__(256) fps_fast(const float* __restrict__ pos,
                                                int n, int m,
                                                float* __restrict__ qpos)
{
    constexpr int PAIRS = PTS / 2;
    __shared__ unsigned s_wv[8];
    __shared__ int s_key;

    const int b = blockIdx.x;
    const float* P = pos + (size_t)b * n * 3;
    float* Q = qpos + (size_t)b * m * 3;
    const int tid = threadIdx.x;
    const int lane = tid & 31, wid = tid >> 5;
    const int base = tid * PTS;

    unsigned long long px2[PAIRS], py2[PAIRS], pz2[PAIRS];
    float md[PTS];
#pragma unroll
    for (int j = 0; j < PAIRS; j++) {
        const float* p0 = P + (size_t)(base + 2*j) * 3;
        px2[j] = pack2(p0[0], p0[3]);
        py2[j] = pack2(p0[1], p0[4]);
        pz2[j] = pack2(p0[2], p0[5]);
    }
#pragma unroll
    for (int j = 0; j < PTS; j++) md[j] = __int_as_float(0x7f800000);

    if (tid == 0) s_key = -1;
    __syncthreads();

    float lx = P[0], ly = P[1], lz = P[2];
    if (tid == 0) { Q[0] = lx; Q[1] = ly; Q[2] = lz; }

    for (int it = 1; it < m; it++) {
        unsigned long long nlx = pack2(-lx, -lx);
        unsigned long long nly = pack2(-ly, -ly);
        unsigned long long nlz = pack2(-lz, -lz);
        float bmA = -1.f, bmB = -1.f;
#pragma unroll
        for (int j = 0; j < PAIRS; j++) {
            unsigned long long dx = add2(px2[j], nlx);
            unsigned long long dy = add2(py2[j], nly);
            unsigned long long dz = add2(pz2[j], nlz);
            unsigned long long s = add2(add2(mul2(dx,dx), mul2(dy,dy)), mul2(dz,dz));
            float lo, hi; unpack2(s, lo, hi);
            float m0 = fminf(md[2*j],   lo); md[2*j]   = m0;
            float m1 = fminf(md[2*j+1], hi); md[2*j+1] = m1;
            bmA = fmaxf(bmA, m0);
            bmB = fmaxf(bmB, m1);
        }
        float bm = fmaxf(bmA, bmB);   // >= 0 always; uint compare monotone
        unsigned vm = __reduce_max_sync(0xffffffffu, __float_as_uint(bm));
        if (lane == 0) s_wv[wid] = vm;
        __syncthreads();
        unsigned gv = max(max(max(s_wv[0], s_wv[1]), max(s_wv[2], s_wv[3])),
                          max(max(s_wv[4], s_wv[5]), max(s_wv[6], s_wv[7])));
        if (__float_as_uint(bm) == gv) {
            int loc = PTS;
#pragma unroll
            for (int j = PTS - 1; j >= 0; j--)
                if (__float_as_uint(md[j]) == gv) loc = j;   // keeps smallest j
            if (loc < PTS) atomicMax(&s_key, (it << 12) | (4095 - (base + loc)));
        }
        __syncthreads();
        int gi = 4095 - (s_key & 4095);
        const float* pw = P + (size_t)gi * 3;   // same addr -> broadcast LDG
        lx = pw[0]; ly = pw[1]; lz = pw[2];
        if (tid == 0) {
            Q[(size_t)it*3]   = lx;
            Q[(size_t)it*3+1] = ly;
            Q[(size_t)it*3+2] = lz;
        }
    }
}

// =====================================================================
// Exact 64-NN SET per query via 4-pass radix select on d2 float bits.
// Output order is ARBITRARY (downstream max/any are order-invariant);
// the SET matches lax.top_k exactly: all d2 < T, plus smallest-index
// ties at d2 == T to fill 64 (T = exact 64th smallest, bits monotone).
// =====================================================================
template<int EPT>
__global__ void __launch_bounds__(256) knn_select(const float* __restrict__ src,
                                                  const float* __restrict__ qpos,
                                                  int m,
                                                  int* __restrict__ nidx,
                                                  float* __restrict__ nd2)
{
    __shared__ unsigned bins[256];
    __shared__ unsigned s_b, s_r;
    __shared__ int s_cnt;
    __shared__ int s_last;
    __shared__ unsigned s_min;

    const int n = EPT * 256;
    const int bq = blockIdx.x;
    const int b  = bq / m;
    const float* S = src + (size_t)b * n * 3;
    const int tid = threadIdx.x;

    float qx = qpos[(size_t)bq*3], qy = qpos[(size_t)bq*3+1], qz = qpos[(size_t)bq*3+2];
    unsigned rb[EPT];
#pragma unroll
    for (int j = 0; j < EPT; j++) {
        int i = j*256 + tid;
        float dx = __fadd_rn(S[i*3],   -qx);
        float dy = __fadd_rn(S[i*3+1], -qy);
        float dz = __fadd_rn(S[i*3+2], -qz);
        rb[j] = __float_as_uint(__fadd_rn(__fadd_rn(__fmul_rn(dx,dx), __fmul_rn(dy,dy)),
                                          __fmul_rn(dz,dz)));
    }

    unsigned prefix = 0;
    unsigned rank = 64;
#pragma unroll
    for (int pass = 0; pass < 4; pass++) {
        const int shift = 24 - 8*pass;
        bins[tid] = 0;
        __syncthreads();
#pragma unroll
        for (int j = 0; j < EPT; j++) {
            unsigned v = rb[j];
            bool in = (pass == 0) ? true : ((v >> (shift + 8)) == prefix);
            if (in) atomicAdd(&bins[(v >> shift) & 255], 1u);
        }
        __syncthreads();
        if (tid < 32) {
            unsigned c[8]; unsigned ssum = 0;
#pragma unroll
            for (int t = 0; t < 8; t++) { c[t] = bins[tid*8 + t]; ssum += c[t]; }
            unsigned cum = ssum;
#pragma unroll
            for (int off = 1; off < 32; off <<= 1) {
                unsigned o = __shfl_up_sync(0xffffffffu, cum, off);
                if (tid >= off) cum += o;
            }
            unsigned excl = cum - ssum;
            if (rank > excl && rank <= cum) {
                unsigned rr = rank - excl;
#pragma unroll
                for (int t = 0; t < 8; t++) {
                    if (rr <= c[t]) { s_b = (unsigned)(tid*8 + t); s_r = rr; break; }
                    rr -= c[t];
                }
            }
        }
        __syncthreads();
        prefix = (prefix << 8) | s_b;
        rank = s_r;
        __syncthreads();
    }

    const unsigned T = prefix;
    const int take = (int)rank;

    if (tid == 0) { s_cnt = 0; s_last = -1; }
    __syncthreads();
#pragma unroll
    for (int j = 0; j < EPT; j++) {
        if (rb[j] < T) {
            int slot = atomicAdd(&s_cnt, 1);
            int i = j*256 + tid;
            nidx[(size_t)bq*KNN + slot] = i;
            nd2 [(size_t)bq*KNN + slot] = __uint_as_float(rb[j]);
        }
    }
    __syncthreads();
    const int c_less = s_cnt;
    for (int t = 0; t < take; t++) {
        if (tid == 0) s_min = 0xffffffffu;
        __syncthreads();
        int last = s_last;
#pragma unroll
        for (int j = 0; j < EPT; j++) {
            int i = j*256 + tid;
            if (rb[j] == T && i > last) atomicMin(&s_min, (unsigned)i);
        }
        __syncthreads();
        if (tid == 0) {
            int win = (int)s_min;
            s_last = win;
            nidx[(size_t)bq*KNN + c_less + t] = win;
            nd2 [(size_t)bq*KNN + c_less + t] = __uint_as_float(T);
        }
        __syncthreads();
    }
}

// =====================================================================
// Fully fused SA1 PointConv per query: gather(6) -> Lin6x64+ReLU+BN ->
// Lin64x64+ReLU+BN -> dual-radius masked max -> g_x1[bq][128].
// =====================================================================
__global__ void __launch_bounds__(128) sa1_fused(
    const float* __restrict__ color, const float* __restrict__ xyz,
    const float* __restrict__ w1a, const float* __restrict__ b1a,
    const float* __restrict__ g1a, const float* __restrict__ be1a,
    const float* __restrict__ w1b, const float* __restrict__ b1b,
    const float* __restrict__ g1b, const float* __restrict__ be1b)
{
    __shared__ __align__(16) float feats[64][6];
    __shared__ __align__(16) float Xs[64][66];
    __shared__ __align__(16) float Ws[64][66];
    __shared__ float d2s[64];
    __shared__ float redA[8][64];
    __shared__ float redB[8][64];

    const int bq = blockIdx.x;
    const int tid = threadIdx.x;
    const float bnf = 1.0f / sqrtf(1.0f + 1e-5f);

    if (tid < 64) {
        int r = bq*KNN + tid;
        int pt = g_nidx1[r];
        d2s[tid] = g_nd2_1[r];
        int b = bq >> 11;
        const float* cb = color + ((size_t)b*NPTS + pt) * 3;
        const float* pb = xyz   + ((size_t)b*NPTS + pt) * 3;
        const float* qp = g_qpos1 + (size_t)bq * 3;
        feats[tid][0] = cb[0]; feats[tid][1] = cb[1]; feats[tid][2] = cb[2];
        feats[tid][3] = pb[0] - qp[0];
        feats[tid][4] = pb[1] - qp[1];
        feats[tid][5] = pb[2] - qp[2];
    }
    for (int i = tid; i < 4096; i += 128) Ws[i >> 6][i & 63] = w1b[i];
    __syncthreads();

    {
        int row = tid >> 1;
        int cb0 = (tid & 1) * 32;
        float f0 = feats[row][0], f1 = feats[row][1], f2 = feats[row][2];
        float f3 = feats[row][3], f4 = feats[row][4], f5 = feats[row][5];
#pragma unroll 8
        for (int c = 0; c < 32; c++) {
            int col = cb0 + c;
            float acc = 0.f;
            acc = fmaf(f0, w1a[col],        acc);
            acc = fmaf(f1, w1a[64  + col],  acc);
            acc = fmaf(f2, w1a[128 + col],  acc);
            acc = fmaf(f3, w1a[192 + col],  acc);
            acc = fmaf(f4, w1a[256 + col],  acc);
            acc = fmaf(f5, w1a[320 + col],  acc);
            float v = fmaxf(acc + b1a[col], 0.f);
            Xs[col][row] = v * (g1a[col] * bnf) + be1a[col];
        }
    }
    __syncthreads();

    const int tn = (tid & 15) * 4;
    const int tm = (tid >> 4) * 8;
    unsigned long long acc[4][4];
#pragma unroll
    for (int i = 0; i < 4; i++)
#pragma unroll
        for (int j = 0; j < 4; j++) acc[i][j] = 0ull;

#pragma unroll 4
    for (int k = 0; k < 64; k++) {
        unsigned long long a2[4], b2[4];
#pragma unroll
        for (int i = 0; i < 4; i++)
            a2[i] = *(const unsigned long long*)&Xs[k][tm + 2*i];
#pragma unroll
        for (int j = 0; j < 4; j++) {
            float bv = Ws[k][tn + j];
            asm("mov.b64 %0, {%1, %1};" : "=l"(b2[j]) : "f"(bv));
        }
#pragma unroll
        for (int i = 0; i < 4; i++)
#pragma unroll
            for (int j = 0; j < 4; j++)
                asm("fma.rn.f32x2 %0, %1, %2, %0;"
                    : "+l"(acc[i][j]) : "l"(a2[i]), "l"(b2[j]));
    }

    const float rA = (float)(0.2*0.2), rB = (float)(0.1*0.1);
    const float NEG = -3.402823466e38f;
#pragma unroll
    for (int j = 0; j < 4; j++) {
        int col = tn + j;
        float s = g1b[col] * bnf, t = be1b[col], bi = b1b[col];
        float mA = NEG, mB = NEG;
#pragma unroll
        for (int i = 0; i < 4; i++) {
            float lo, hi; unpack2(acc[i][j], lo, hi);
            int r0 = tm + 2*i;
            float vlo = fmaxf(lo + bi, 0.f) * s + t;
            float vhi = fmaxf(hi + bi, 0.f) * s + t;
            float dA = d2s[r0], dB = d2s[r0+1];
            if (dA <= rA) mA = fmaxf(mA, vlo);
            if (dA <= rB) mB = fmaxf(mB, vlo);
            if (dB <= rA) mA = fmaxf(mA, vhi);
            if (dB <= rB) mB = fmaxf(mB, vhi);
        }
        redA[tid >> 4][col] = mA;
        redB[tid >> 4][col] = mB;
    }
    __syncthreads();
    if (tid < 64) {
        float a = NEG, c = NEG;
#pragma unroll
        for (int g = 0; g < 8; g++) {
            a = fmaxf(a, redA[g][tid]);
            c = fmaxf(c, redB[g][tid]);
        }
        g_x1[(size_t)bq*128 + tid]      = (a > -1e30f) ? a : 0.f;
        g_x1[(size_t)bq*128 + 64 + tid] = (c > -1e30f) ? c : 0.f;
    }
}

// =====================================================================
// Gather kernels for SA2 / mlp3 inputs
// =====================================================================
__global__ void gather2_kernel()
{
    int gt = blockIdx.x * 256 + threadIdx.x;
    int w = gt >> 5, lane = gt & 31;
    if (w >= R2) return;
    int b = w / (M2 * KNN);
    int q = (w / KNN) % M2;
    int n = g_nidx2[w];
    const float* xr = g_x1 + ((size_t)(b*M1 + n)) * 128;
    float* o = g_bufX + (size_t)w * 131;
#pragma unroll
    for (int i = 0; i < 4; i++) o[lane + 32*i] = xr[lane + 32*i];
    if (lane < 3)
        o[128 + lane] = g_qpos1[((size_t)(b*M1 + n))*3 + lane]
                      - g_qpos2[((size_t)(b*M2 + q))*3 + lane];
}

__global__ void gather3_kernel()
{
    int e = blockIdx.x * 256 + threadIdx.x;
    if (e >= R3 * 515) return;
    int row = e / 515, c = e % 515;
    g_bufX[e] = (c < 512) ? g_x2[(size_t)row*512 + c]
                          : g_qpos2[(size_t)row*3 + (c - 512)];
}

// =====================================================================
// Tiled SGEMM Y = bn(relu(X @ W + bias)) with packed fma.rn.f32x2.
// =====================================================================
#define BKK 16
__global__ void __launch_bounds__(128) gemm_bn(const float* __restrict__ X,
    const float* __restrict__ W, const float* __restrict__ bias,
    const float* __restrict__ gamma, const float* __restrict__ beta,
    float* __restrict__ Y, int M, int K, int N)
{
    __shared__ __align__(16) float As[BKK][64 + 4];
    __shared__ __align__(16) float Bs[BKK][64 + 4];
    const int tid = threadIdx.x;
    const int bm = blockIdx.y * 64, bn = blockIdx.x * 64;
    const int tn = (tid & 15) * 4;
    const int tm = (tid >> 4) * 8;

    unsigned long long acc[4][4];
#pragma unroll
    for (int i = 0; i < 4; i++)
#pragma unroll
        for (int j = 0; j < 4; j++) acc[i][j] = 0ull;

    for (int k0 = 0; k0 < K; k0 += BKK) {
#pragma unroll
        for (int i = 0; i < 8; i++) {
            int t = i*128 + tid;
            int m = t >> 4, k = t & 15;
            float v = 0.f;
            int gr = bm + m, gk = k0 + k;
            if (gr < M && gk < K) v = X[(size_t)gr*K + gk];
            As[k][m] = v;
        }
#pragma unroll
        for (int i = 0; i < 8; i++) {
            int t = i*128 + tid;
            int k = t >> 6, n = t & 63;
            float v = 0.f;
            int gk = k0 + k;
            if (gk < K) v = W[(size_t)gk*N + bn + n];
            Bs[k][n] = v;
        }
        __syncthreads();
#pragma unroll
        for (int kk = 0; kk < BKK; kk++) {
            unsigned long long a2[4], b2[4];
#pragma unroll
            for (int i = 0; i < 4; i++)
                a2[i] = *(const unsigned long long*)&As[kk][tm + 2*i];
#pragma unroll
            for (int j = 0; j < 4; j++) {
                float bv = Bs[kk][tn + j];
                asm("mov.b64 %0, {%1, %1};" : "=l"(b2[j]) : "f"(bv));
            }
#pragma unroll
            for (int i = 0; i < 4; i++)
#pragma unroll
                for (int j = 0; j < 4; j++)
                    asm("fma.rn.f32x2 %0, %1, %2, %0;"
                        : "+l"(acc[i][j]) : "l"(a2[i]), "l"(b2[j]));
        }
        __syncthreads();
    }

    const float bnf = 1.0f / sqrtf(1.0f + 1e-5f);
    float s[4], t[4], bi[4];
#pragma unroll
    for (int j = 0; j < 4; j++) {
        int c = bn + tn + j;
        s[j] = gamma[c] * bnf; t[j] = beta[c]; bi[j] = bias[c];
    }
#pragma unroll
    for (int i = 0; i < 4; i++) {
#pragma unroll
        for (int j = 0; j < 4; j++) {
            float lo, hi; unpack2(acc[i][j], lo, hi);
            int r0 = bm + tm + 2*i;
            if (r0 < M) {
                float v = fmaxf(lo + bi[j], 0.f);
                Y[(size_t)r0*N + bn + tn + j] = v * s[j] + t[j];
            }
            if (r0 + 1 < M) {
                float v = fmaxf(hi + bi[j], 0.f);
                Y[(size_t)(r0+1)*N + bn + tn + j] = v * s[j] + t[j];
            }
        }
    }
}

// =====================================================================
// SA2 layer-2 GEMM (K=128, N=256) with FUSED dual-radius masked max.
// =====================================================================
__global__ void __launch_bounds__(128) gemm_bn_max2(const float* __restrict__ X,
    const float* __restrict__ W, const float* __restrict__ bias,
    const float* __restrict__ gamma, const float* __restrict__ beta)
{
    __shared__ __align__(16) float As[BKK][64 + 4];
    __shared__ __align__(16) float Bs[BKK][64 + 4];
    __shared__ float d2s[64];
    __shared__ float redA[8][64];
    __shared__ float redB[8][64];
    const int K = 128, N = 256;
    const int tid = threadIdx.x;
    const int bq = blockIdx.y;
    const int bm = bq * 64, bn = blockIdx.x * 64;
    const int tn = (tid & 15) * 4;
    const int tm = (tid >> 4) * 8;

    if (tid < 64) d2s[tid] = g_nd2_2[(size_t)bq*KNN + tid];

    unsigned long long acc[4][4];
#pragma unroll
    for (int i = 0; i < 4; i++)
#pragma unroll
        for (int j = 0; j < 4; j++) acc[i][j] = 0ull;

    for (int k0 = 0; k0 < K; k0 += BKK) {
#pragma unroll
        for (int i = 0; i < 8; i++) {
            int t = i*128 + tid;
            int m = t >> 4, k = t & 15;
            As[k][m] = X[(size_t)(bm + m)*K + k0 + k];
        }
#pragma unroll
        for (int i = 0; i < 8; i++) {
            int t = i*128 + tid;
            int k = t >> 6, n = t & 63;
            Bs[k][n] = W[(size_t)(k0 + k)*N + bn + n];
        }
        __syncthreads();
#pragma unroll
        for (int kk = 0; kk < BKK; kk++) {
            unsigned long long a2[4], b2[4];
#pragma unroll
            for (int i = 0; i < 4; i++)
                a2[i] = *(const unsigned long long*)&As[kk][tm + 2*i];
#pragma unroll
            for (int j = 0; j < 4; j++) {
                float bv = Bs[kk][tn + j];
                asm("mov.b64 %0, {%1, %1};" : "=l"(b2[j]) : "f"(bv));
            }
#pragma unroll
            for (int i = 0; i < 4; i++)
#pragma unroll
                for (int j = 0; j < 4; j++)
                    asm("fma.rn.f32x2 %0, %1, %2, %0;"
                        : "+l"(acc[i][j]) : "l"(a2[i]), "l"(b2[j]));
        }
        __syncthreads();
    }

    const float bnf = 1.0f / sqrtf(1.0f + 1e-5f);
    const float rA = (float)(0.35*0.35), rB = (float)(0.5*0.5);
    const float NEG = -3.402823466e38f;
#pragma unroll
    for (int j = 0; j < 4; j++) {
        int c = bn + tn + j;
        float s = gamma[c] * bnf, t = beta[c], bi = bias[c];
        float mA = NEG, mB = NEG;
#pragma unroll
        for (int i = 0; i < 4; i++) {
            float lo, hi; unpack2(acc[i][j], lo, hi);
            int r0 = tm + 2*i;
            float vlo = fmaxf(lo + bi, 0.f) * s + t;
            float vhi = fmaxf(hi + bi, 0.f) * s + t;
            float dA = d2s[r0], dB = d2s[r0+1];
            if (dA <= rA) mA = fmaxf(mA, vlo);
            if (dA <= rB) mB = fmaxf(mB, vlo);
            if (dB <= rA) mA = fmaxf(mA, vhi);
            if (dB <= rB) mB = fmaxf(mB, vhi);
        }
        redA[tid >> 4][tn + j] = mA;
        redB[tid >> 4][tn + j] = mB;
    }
    __syncthreads();
    if (tid < 64) {
        float a = NEG, c = NEG;
#pragma unroll
        for (int g = 0; g < 8; g++) {
            a = fmaxf(a, redA[g][tid]);
            c = fmaxf(c, redB[g][tid]);
        }
        g_x2[(size_t)bq*512 + bn + tid]       = (a > -1e30f) ? a : 0.f;
        g_x2[(size_t)bq*512 + 256 + bn + tid] = (c > -1e30f) ? c : 0.f;
    }
}

__global__ void globalmax_kernel()
{
    int f = blockIdx.x * 256 + threadIdx.x;
    int b = blockIdx.y;
    float m = -3.402823466e38f;
    for (int q = 0; q < M2; q++)
        m = fmaxf(m, g_bufA[((size_t)(b*M2 + q))*1024 + f]);
    g_glob[(size_t)b*1024 + f] = m;
}

// =====================================================================
// Head: h1 = relu(g @ wl1 + bl1); out = h1 @ wl2 + bl2; L2-normalize.
// =====================================================================
__global__ void __launch_bounds__(512) head_kernel(
    const float* __restrict__ wl1, const float* __restrict__ bl1,
    const float* __restrict__ wl2, const float* __restrict__ bl2,
    float* __restrict__ out)
{
    __shared__ float sg[1024];
    __shared__ float sh[512];
    __shared__ float so[128];
    __shared__ float snorm;
    int b = blockIdx.x, tid = threadIdx.x;
    sg[tid]       = g_glob[(size_t)b*1024 + tid];
    sg[tid + 512] = g_glob[(size_t)b*1024 + 512 + tid];
    __syncthreads();

    float acc = bl1[tid];
    for (int k = 0; k < 1024; k++) acc = fmaf(sg[k], wl1[(size_t)k*512 + tid], acc);
    sh[tid] = fmaxf(acc, 0.f);
    __syncthreads();

    if (tid < 128) {
        float o = bl2[tid];
        for (int k = 0; k < 512; k++) o = fmaf(sh[k], wl2[(size_t)k*128 + tid], o);
        so[tid] = o;
    }
    __syncthreads();
    if (tid < 32) {
        float s = 0.f;
        for (int c = tid; c < 128; c += 32) s += so[c] * so[c];
#pragma unroll
        for (int off = 16; off > 0; off >>= 1) s += __shfl_down_sync(0xffffffffu, s, off);
        if (tid == 0) snorm = sqrtf(s);
    }
    __syncthreads();
    if (tid < 128) out[(size_t)b*128 + tid] = so[tid] / snorm;
}

// =====================================================================
extern "C" void kernel_launch(void* const* d_in, const int* in_sizes, int n_in,
                              void* d_out, int out_size)
{
    const float* xyz   = (const float*)d_in[0];
    const float* color = (const float*)d_in[1];
    const float* w1a = (const float*)d_in[2],  *b1a = (const float*)d_in[3];
    const float* g1a = (const float*)d_in[4],  *be1a = (const float*)d_in[5];
    const float* w1b = (const float*)d_in[6],  *b1b = (const float*)d_in[7];
    const float* g1b = (const float*)d_in[8],  *be1b = (const float*)d_in[9];
    const float* w2a = (const float*)d_in[10], *b2a = (const float*)d_in[11];
    const float* g2a = (const float*)d_in[12], *be2a = (const float*)d_in[13];
    const float* w2b = (const float*)d_in[14], *b2b = (const float*)d_in[15];
    const float* g2b = (const float*)d_in[16], *be2b = (const float*)d_in[17];
    const float* w3  = (const float*)d_in[18], *b3  = (const float*)d_in[19];
    const float* g3  = (const float*)d_in[20], *be3 = (const float*)d_in[21];
    const float* wl1 = (const float*)d_in[22], *bl1 = (const float*)d_in[23];
    const float* wl2 = (const float*)d_in[24], *bl2 = (const float*)d_in[25];
    float* out = (float*)d_out;

    void *vQ1, *vQ2, *vN1, *vD1, *vN2, *vD2, *vX, *vA;
    cudaGetSymbolAddress(&vQ1, g_qpos1);
    cudaGetSymbolAddress(&vQ2, g_qpos2);
    cudaGetSymbolAddress(&vN1, g_nidx1);
    cudaGetSymbolAddress(&vD1, g_nd2_1);
    cudaGetSymbolAddress(&vN2, g_nidx2);
    cudaGetSymbolAddress(&vD2, g_nd2_2);
    cudaGetSymbolAddress(&vX, g_bufX);
    cudaGetSymbolAddress(&vA, g_bufA);
    float* aQ1 = (float*)vQ1; float* aQ2 = (float*)vQ2;
    int* aN1 = (int*)vN1; float* aD1 = (float*)vD1;
    int* aN2 = (int*)vN2; float* aD2 = (float*)vD2;
    float* aX = (float*)vX; float* aA = (float*)vA;

    // ---- SA module 1 (fully fused conv) ----
    fps_fast<16><<<BATCH, 256>>>(xyz, NPTS, M1, aQ1);
    knn_select<16><<<BATCH*M1, 256>>>(xyz, aQ1, M1, aN1, aD1);
    sa1_fused<<<BATCH*M1, 128>>>(color, xyz, w1a, b1a, g1a, be1a,
                                 w1b, b1b, g1b, be1b);

    // ---- SA module 2 ----
    fps_fast<8><<<BATCH, 256>>>(aQ1, M1, M2, aQ2);
    knn_select<8><<<BATCH*M2, 256>>>(aQ1, aQ2, M2, aN2, aD2);
    gather2_kernel<<<(R2*32)/256, 256>>>();
    gemm_bn<<<dim3(2, R2/64), 128>>>(aX, w2a, b2a, g2a, be2a, aA, R2, 131, 128);
    gemm_bn_max2<<<dim3(4, R2/64), 128>>>(aA, w2b, b2b, g2b, be2b);

    // ---- mlp3 + global max + head ----
    gather3_kernel<<<(R3*515 + 255)/256, 256>>>();
    gemm_bn<<<dim3(16, (R3 + 63)/64), 128>>>(aX, w3, b3, g3, be3, aA, R3, 515, 1024);
    globalmax_kernel<<<dim3(4, BATCH), 256>>>();
    head_kernel<<<BATCH, 512>>>(wl1, bl1, wl2, bl2, out);
}